// round 11
// baseline (speedup 1.0000x reference)
#include <cuda_runtime.h>
#include <cuda.h>
#include <cuda_bf16.h>
#include <cstdint>

typedef __nv_bfloat16 bf16;

#if defined(__CUDA_ARCH__) && (__CUDA_ARCH__ == 1030) && \
    (defined(__CUDA_ARCH_FEAT_SM103_ALL) || defined(__CUDA_ARCH_FEAT_SM100_ALL))
#define TC_OK 1
#else
#define TC_OK 0
#endif

#define DIMV 768
#define HIDV 2048
#define TOKV 4096
#define NEXP 8
#define MAXGRP 24
#define NTILE (MAXGRP*2)      // 48 row-tiles of 128
#define MAXROWS (MAXGRP*256)
#define KC 32                 // stage K elems (64B rows, SW64)

// ------------------------- device scratch ---------------------------------
__device__ bf16 gW1h[(size_t)NEXP*HIDV*DIMV];
__device__ bf16 gW1l[(size_t)NEXP*HIDV*DIMV];
__device__ bf16 gW2h[(size_t)NEXP*HIDV*DIMV];
__device__ bf16 gW2l[(size_t)NEXP*HIDV*DIMV];
__device__ bf16 gW3h[(size_t)NEXP*DIMV*HIDV];
__device__ bf16 gW3l[(size_t)NEXP*DIMV*HIDV];
__device__ bf16 gXh[(size_t)MAXROWS*DIMV];
__device__ bf16 gXl[(size_t)MAXROWS*DIMV];
__device__ bf16 gUh[(size_t)MAXROWS*HIDV];
__device__ bf16 gUl[(size_t)MAXROWS*HIDV];
__device__ int   gTokE[TOKV];
__device__ float gP[TOKV];
__device__ int   gRowTok[MAXROWS];
__device__ int   gGrpE[MAXGRP];
__device__ int   gDone;

// ------------------------- common helpers ----------------------------------
__device__ __forceinline__ uint32_t smem_u32(const void* p) {
    uint32_t a;
    asm("{ .reg .u64 t; cvta.to.shared.u64 t, %1; cvt.u32.u64 %0, t; }" : "=r"(a) : "l"(p));
    return a;
}
__device__ __forceinline__ void split2(float v, bf16& h, bf16& l) {
    h = __float2bfloat16(v);
    l = __float2bfloat16(v - __bfloat162float(h));
}

// ------------------------- tcgen05 / TMA helpers ---------------------------
__device__ __forceinline__ uint32_t elect1() {
    uint32_t p = 0;
#if TC_OK
    asm volatile("{ .reg .pred p; elect.sync _|p, 0xFFFFFFFF; selp.b32 %0,1,0,p; }" : "=r"(p));
#endif
    return p;
}
__device__ __forceinline__ uint64_t desc64(uint32_t addr) {
    // SW64: layout=4, version=1, SBO=32 (512B), LBO=1 (16B) — validated R5
    const uint64_t base = (uint64_t(4) << 61) | (uint64_t(1) << 46)
                        | (uint64_t(32) << 32) | (uint64_t(1) << 16);
    return base | ((uint64_t)(addr >> 4) & 0x3FFF);
}
#define IDESC 0x8200490u   // kind::f16, bf16 x bf16 -> f32, M=128, N=128

__device__ __forceinline__ void mma_ss(uint32_t d, uint64_t ad, uint64_t bd, uint32_t en) {
#if TC_OK
    asm volatile(
        "{\n .reg .pred p;\n setp.ne.u32 p, %4, 0;\n"
        " tcgen05.mma.cta_group::1.kind::f16 [%0], %1, %2, %3, {%5,%5,%5,%5}, p;\n}"
        :: "r"(d), "l"(ad), "l"(bd), "r"(IDESC), "r"(en), "r"(0u) : "memory");
#endif
}
__device__ __forceinline__ void mma_commit(uint32_t mbar) {
#if TC_OK
    asm volatile(
        "tcgen05.commit.cta_group::1.mbarrier::arrive::one.shared::cluster.b64 [%0];"
        :: "r"(mbar) : "memory");
#endif
}
__device__ __forceinline__ void tma2d(uint32_t smem, const CUtensorMap* map,
                                      int x, int y, uint32_t mbar) {
#if TC_OK
    asm volatile(
        "cp.async.bulk.tensor.2d.shared::cta.global.tile.mbarrier::complete_tx::bytes "
        "[%0], [%1, {%2, %3}], [%4];"
        :: "r"(smem), "l"(map), "r"(x), "r"(y), "r"(mbar) : "memory");
#endif
}
__device__ __forceinline__ void expect_tx(uint32_t mbar, uint32_t bytes) {
#if TC_OK
    asm volatile("mbarrier.arrive.expect_tx.shared.b64 _, [%0], %1;"
                 :: "r"(mbar), "r"(bytes) : "memory");
#endif
}
__device__ __forceinline__ void mbar_init(uint32_t a, uint32_t c) {
#if TC_OK
    asm volatile("mbarrier.init.shared.b64 [%0], %1;" :: "r"(a), "r"(c) : "memory");
#endif
}
__device__ __forceinline__ void mbar_inval(uint32_t a) {
#if TC_OK
    asm volatile("mbarrier.inval.shared.b64 [%0];" :: "r"(a) : "memory");
#endif
}
__device__ __forceinline__ void mbar_wait(uint32_t a, uint32_t ph) {
#if TC_OK
    uint32_t ok = 0;
    while (!ok) {
        asm volatile(
            "{\n .reg .pred P;\n"
            " mbarrier.try_wait.parity.acquire.cta.shared::cta.b64 P, [%1], %2, 0x989680;\n"
            " selp.b32 %0, 1, 0, P;\n}"
            : "=r"(ok) : "r"(a), "r"(ph) : "memory");
    }
#endif
}
__device__ __forceinline__ void tmem_alloc(uint32_t smem_ptr, uint32_t ncols) {
#if TC_OK
    asm volatile("tcgen05.alloc.cta_group::1.sync.aligned.shared::cta.b32 [%0], %1;"
                 :: "r"(smem_ptr), "r"(ncols) : "memory");
#endif
}
__device__ __forceinline__ void tmem_dealloc(uint32_t tmem, uint32_t ncols) {
#if TC_OK
    asm volatile("tcgen05.relinquish_alloc_permit.cta_group::1.sync.aligned;");
    asm volatile("tcgen05.dealloc.cta_group::1.sync.aligned.b32 %0, %1;" :: "r"(tmem), "r"(ncols));
#endif
}
__device__ __forceinline__ void ldtm32(uint32_t* r, uint32_t ta) {
#if TC_OK
    asm volatile(
        "tcgen05.ld.sync.aligned.32x32b.x32.b32 "
        "{%0,%1,%2,%3,%4,%5,%6,%7,%8,%9,%10,%11,%12,%13,%14,%15,"
        "%16,%17,%18,%19,%20,%21,%22,%23,%24,%25,%26,%27,%28,%29,%30,%31}, [%32];"
        : "=r"(r[0]), "=r"(r[1]), "=r"(r[2]), "=r"(r[3]), "=r"(r[4]), "=r"(r[5]),
          "=r"(r[6]), "=r"(r[7]), "=r"(r[8]), "=r"(r[9]), "=r"(r[10]), "=r"(r[11]),
          "=r"(r[12]), "=r"(r[13]), "=r"(r[14]), "=r"(r[15]), "=r"(r[16]), "=r"(r[17]),
          "=r"(r[18]), "=r"(r[19]), "=r"(r[20]), "=r"(r[21]), "=r"(r[22]), "=r"(r[23]),
          "=r"(r[24]), "=r"(r[25]), "=r"(r[26]), "=r"(r[27]), "=r"(r[28]), "=r"(r[29]),
          "=r"(r[30]), "=r"(r[31])
        : "r"(ta));
#endif
}
__device__ __forceinline__ void tm_wait_ld() {
#if TC_OK
    asm volatile("tcgen05.wait::ld.sync.aligned;" ::: "memory");
#endif
}
__device__ __forceinline__ void tm_fence_after() {
#if TC_OK
    asm volatile("tcgen05.fence::after_thread_sync;" ::: "memory");
#endif
}

// ================= launch 0: all weight transposes + split =================
__global__ void tsplit_all_k(const float* __restrict__ w1,
                             const float* __restrict__ w2,
                             const float* __restrict__ w3) {
    __shared__ float tile[64][65];
    int z = blockIdx.z;
    if (z == 0 && blockIdx.x == 0 && blockIdx.y == 0 && threadIdx.x == 0) gDone = 0;
    int R, C, e;
    const float* src;
    bf16 *dh, *dl;
    if (z < 16) {
        R = DIMV; C = HIDV; e = z & 7;
        src = (z < 8) ? w1 : w2;
        dh = (z < 8) ? gW1h : gW2h;
        dl = (z < 8) ? gW1l : gW2l;
        if ((int)blockIdx.y >= R / 64) return;
    } else {
        R = HIDV; C = DIMV; e = z - 16;
        src = w3; dh = gW3h; dl = gW3l;
        if ((int)blockIdx.x >= C / 64) return;
    }
    int c0 = blockIdx.x * 64, r0 = blockIdx.y * 64;
    int tid = threadIdx.x;
    const float* s = src + (size_t)e * R * C;
#pragma unroll
    for (int i = 0; i < 16; i++) {
        int idx = i * 256 + tid;
        int r = idx >> 6, c = idx & 63;
        tile[r][c] = s[(size_t)(r0 + r) * C + c0 + c];
    }
    __syncthreads();
    bf16* dhp = dh + (size_t)e * C * R;
    bf16* dlp = dl + (size_t)e * C * R;
#pragma unroll
    for (int i = 0; i < 8; i++) {
        int idx = i * 256 + tid;
        int c = idx >> 5, rp = idx & 31, r = rp * 2;
        float v0 = tile[r][c], v1 = tile[r + 1][c];
        bf16 h0, l0, h1, l1;
        split2(v0, h0, l0);
        split2(v1, h1, l1);
        __nv_bfloat162 vh; vh.x = h0; vh.y = h1;
        __nv_bfloat162 vl; vl.x = l0; vl.y = l1;
        size_t o = (size_t)(c0 + c) * R + r0 + r;
        *(__nv_bfloat162*)(dhp + o) = vh;
        *(__nv_bfloat162*)(dlp + o) = vl;
    }
}

// ========== launch 1: router + (last block) plan ===========================
__global__ void routerplan_k(const float* __restrict__ x,
                             const float* __restrict__ rw,
                             const float* __restrict__ rb) {
    int tid = threadIdx.x;
    int warp = tid >> 5, lane = tid & 31;
    int tok = blockIdx.x * 8 + warp;
    {
        const float* xr = x + (size_t)tok * DIMV;
        float acc[NEXP];
#pragma unroll
        for (int e = 0; e < NEXP; e++) acc[e] = 0.f;
        for (int k = lane; k < DIMV; k += 32) {
            float xv = xr[k];
            const float* w = rw + k * NEXP;
#pragma unroll
            for (int e = 0; e < NEXP; e++) acc[e] += xv * w[e];
        }
#pragma unroll
        for (int off = 16; off; off >>= 1)
#pragma unroll
            for (int e = 0; e < NEXP; e++)
                acc[e] += __shfl_xor_sync(0xffffffffu, acc[e], off);
        if (lane == 0) {
            float l[NEXP];
            float m = -1e30f; int mi = 0;
#pragma unroll
            for (int e = 0; e < NEXP; e++) {
                l[e] = acc[e] + rb[e];
                if (l[e] > m) { m = l[e]; mi = e; }
            }
            float s = 0.f;
#pragma unroll
            for (int e = 0; e < NEXP; e++) s += expf(l[e] - m);
            gTokE[tok] = mi;
            gP[tok] = 1.f / s;
        }
    }
    __shared__ int sLast;
    __threadfence();
    __syncthreads();
    if (tid == 0) {
        int v = atomicAdd(&gDone, 1);
        sLast = (v == (int)gridDim.x - 1) ? 1 : 0;
    }
    __syncthreads();
    if (!sLast) return;

    __shared__ int cnt[NEXP], cur[NEXP], base[NEXP];
    if (tid < NEXP) { cnt[tid] = 0; cur[tid] = 0; }
    __syncthreads();
    for (int t = tid; t < TOKV; t += 256) atomicAdd(&cnt[gTokE[t]], 1);
    __syncthreads();
    if (tid == 0) {
        int acc = 0, gc = 0;
        for (int e = 0; e < NEXP; e++) {
            base[e] = acc;
            int ng = (cnt[e] + 255) >> 8;
            for (int i = 0; i < ng && gc < MAXGRP; i++) gGrpE[gc++] = e;
            acc += ng * 256;
        }
        for (; gc < MAXGRP; gc++) gGrpE[gc] = 0;
    }
    __syncthreads();
    for (int r = tid; r < MAXROWS; r += 256) gRowTok[r] = -1;
    __syncthreads();
    for (int t = tid; t < TOKV; t += 256) {
        int e = gTokE[t];
        int s = atomicAdd(&cur[e], 1);
        gRowTok[base[e] + s] = t;
    }
}

// ================= launch 2: gather X + split ==============================
__global__ void gather_k(const float* __restrict__ x) {
    int row = blockIdx.x;
    int tok = gRowTok[row];
    for (int k = threadIdx.x; k < DIMV; k += blockDim.x) {
        float v = (tok >= 0) ? x[(size_t)tok * DIMV + k] : 0.f;
        bf16 h, l; split2(v, h, l);
        gXh[(size_t)row * DIMV + k] = h;
        gXl[(size_t)row * DIMV + k] = l;
    }
}

// ========= GEMM1: M=128/CTA, TMA warp-specialized, depth 2, 2 CTA/SM =======
// smem: [0] tmem ptr, full[2]@16, empty[2]@64, done@112
// stage (48KB): Ah Al (8KB) B1h B1l B2h B2l (8KB each)
#define G1_STG 49152
#define G1_SMEM (1024 + 2*G1_STG)

__global__ __launch_bounds__(256) void gemm1_tc(
    const __grid_constant__ CUtensorMap mXh, const __grid_constant__ CUtensorMap mXl,
    const __grid_constant__ CUtensorMap mW1h, const __grid_constant__ CUtensorMap mW1l,
    const __grid_constant__ CUtensorMap mW2h, const __grid_constant__ CUtensorMap mW2l) {
#if TC_OK
    extern __shared__ char smem[];
    uint32_t sb = smem_u32(smem);
    int tid = threadIdx.x, wid = tid >> 5, lane = tid & 31;
    int tile = blockIdx.y, nb0 = blockIdx.x * 128;
    int e = gGrpE[tile >> 1];

    if (wid == 0) tmem_alloc(sb, 256);
    if (tid == 0) {
#pragma unroll
        for (int i = 0; i < 2; i++) {
            mbar_init(sb + 16 + i * 8, 1);  // full
            mbar_init(sb + 64 + i * 8, 1);  // empty
        }
        mbar_init(sb + 112, 1);             // done
    }
    __syncthreads();
    uint32_t tmem;
    asm volatile("ld.shared.b32 %0, [%1];" : "=r"(tmem) : "r"(sb));

    const int NS = DIMV / KC;  // 24
    if (wid == 0 && elect1()) {             // producer
        int aY = tile * 128, bY = e * HIDV + nb0;
        for (int s = 0; s < NS; s++) {
            int b = s & 1;
            if (s >= 2) mbar_wait(sb + 64 + b * 8, (uint32_t)(((s - 2) >> 1) & 1));
            uint32_t st = sb + 1024 + b * G1_STG;
            uint32_t fb = sb + 16 + b * 8;
            int kc = s * KC;
            expect_tx(fb, 49152);
            tma2d(st,         &mXh,  kc, aY, fb);
            tma2d(st + 8192,  &mXl,  kc, aY, fb);
            tma2d(st + 16384, &mW1h, kc, bY, fb);
            tma2d(st + 24576, &mW1l, kc, bY, fb);
            tma2d(st + 32768, &mW2h, kc, bY, fb);
            tma2d(st + 40960, &mW2l, kc, bY, fb);
        }
    }
    if (wid == 1) {                          // consumer (MMA)
        for (int s = 0; s < NS; s++) {
            int b = s & 1;
            mbar_wait(sb + 16 + b * 8, (uint32_t)((s >> 1) & 1));
            if (elect1()) {
                uint32_t st = sb + 1024 + b * G1_STG;
                uint64_t ah = desc64(st), al = desc64(st + 8192);
                uint64_t b1h = desc64(st + 16384), b1l = desc64(st + 24576);
                uint64_t b2h = desc64(st + 32768), b2l = desc64(st + 40960);
                uint32_t D1 = tmem, D2 = tmem + 128;
#pragma unroll
                for (int k = 0; k < 2; k++) {
                    uint32_t en = (s == 0 && k == 0) ? 0u : 1u;
                    uint64_t k2 = (uint64_t)(k * 2);
                    mma_ss(D1, ah + k2, b1h + k2, en);
                    mma_ss(D1, ah + k2, b1l + k2, 1u);
                    mma_ss(D1, al + k2, b1h + k2, 1u);
                    mma_ss(D2, ah + k2, b2h + k2, en);
                    mma_ss(D2, ah + k2, b2l + k2, 1u);
                    mma_ss(D2, al + k2, b2h + k2, 1u);
                }
                mma_commit(sb + 64 + b * 8);
            }
        }
        if (elect1()) mma_commit(sb + 112);
    }

    mbar_wait(sb + 112, 0);
    tm_fence_after();

    {
        int sub = wid & 3, chalf = wid >> 2;
        int grow = tile * 128 + sub * 32 + lane;
        bf16* dh = gUh + (size_t)grow * HIDV + nb0 + chalf * 64;
        bf16* dl = gUl + (size_t)grow * HIDV + nb0 + chalf * 64;
#pragma unroll
        for (int p = 0; p < 2; p++) {
            uint32_t r1[32], r2[32];
            ldtm32(r1, tmem + chalf * 64 + p * 32);
            ldtm32(r2, tmem + 128 + chalf * 64 + p * 32);
            tm_wait_ld();
#pragma unroll
            for (int j = 0; j < 32; j += 2) {
                float h1a = __uint_as_float(r1[j]),     h2a = __uint_as_float(r2[j]);
                float h1b = __uint_as_float(r1[j + 1]), h2b = __uint_as_float(r2[j + 1]);
                float ua = h1a * (1.f / (1.f + expf(-h1a))) * h2a;
                float ub = h1b * (1.f / (1.f + expf(-h1b))) * h2b;
                bf16 ha, la, hb, lb;
                split2(ua, ha, la);
                split2(ub, hb, lb);
                __nv_bfloat162 vh; vh.x = ha; vh.y = hb;
                __nv_bfloat162 vl; vl.x = la; vl.y = lb;
                *(__nv_bfloat162*)(dh + p * 32 + j) = vh;
                *(__nv_bfloat162*)(dl + p * 32 + j) = vl;
            }
        }
    }
    __syncthreads();
    if (tid == 0) {
#pragma unroll
        for (int i = 0; i < 2; i++) { mbar_inval(sb + 16 + i * 8); mbar_inval(sb + 64 + i * 8); }
        mbar_inval(sb + 112);
    }
    __syncthreads();
    if (wid == 0) tmem_dealloc(tmem, 256);
#endif
}

// ========= GEMM2: M=128/CTA, TMA warp-specialized, depth 3, 2 CTA/SM =======
// stage (32KB): Ah Al Bh Bl (8KB each)
#define G2_STG 32768
#define G2_SMEM (1024 + 3*G2_STG)

__global__ __launch_bounds__(256) void gemm2_tc(
    float* __restrict__ out,
    const __grid_constant__ CUtensorMap mUh, const __grid_constant__ CUtensorMap mUl,
    const __grid_constant__ CUtensorMap mW3h, const __grid_constant__ CUtensorMap mW3l) {
#if TC_OK
    extern __shared__ char smem[];
    uint32_t sb = smem_u32(smem);
    int tid = threadIdx.x, wid = tid >> 5, lane = tid & 31;
    int tile = blockIdx.y, nb0 = blockIdx.x * 128;
    int e = gGrpE[tile >> 1];

    if (wid == 0) tmem_alloc(sb, 128);
    if (tid == 0) {
#pragma unroll
        for (int i = 0; i < 3; i++) {
            mbar_init(sb + 16 + i * 8, 1);
            mbar_init(sb + 64 + i * 8, 1);
        }
        mbar_init(sb + 112, 1);
    }
    __syncthreads();
    uint32_t tmem;
    asm volatile("ld.shared.b32 %0, [%1];" : "=r"(tmem) : "r"(sb));

    const int NS = HIDV / KC;  // 64
    if (wid == 0 && elect1()) {
        int aY = tile * 128, bY = e * DIMV + nb0;
        for (int s = 0; s < NS; s++) {
            int b = s % 3;
            if (s >= 3) mbar_wait(sb + 64 + b * 8, (uint32_t)(((s - 3) / 3) & 1));
            uint32_t st = sb + 1024 + b * G2_STG;
            uint32_t fb = sb + 16 + b * 8;
            int kc = s * KC;
            expect_tx(fb, 32768);
            tma2d(st,         &mUh,  kc, aY, fb);
            tma2d(st + 8192,  &mUl,  kc, aY, fb);
            tma2d(st + 16384, &mW3h, kc, bY, fb);
            tma2d(st + 24576, &mW3l, kc, bY, fb);
        }
    }
    if (wid == 1) {
        for (int s = 0; s < NS; s++) {
            int b = s % 3;
            mbar_wait(sb + 16 + b * 8, (uint32_t)((s / 3) & 1));
            if (elect1()) {
                uint32_t st = sb + 1024 + b * G2_STG;
                uint64_t ah = desc64(st), al = desc64(st + 8192);
                uint64_t bh = desc64(st + 16384), bl = desc64(st + 24576);
#pragma unroll
                for (int k = 0; k < 2; k++) {
                    uint32_t en = (s == 0 && k == 0) ? 0u : 1u;
                    uint64_t k2 = (uint64_t)(k * 2);
                    mma_ss(tmem, ah + k2, bh + k2, en);
                    mma_ss(tmem, ah + k2, bl + k2, 1u);
                    mma_ss(tmem, al + k2, bh + k2, 1u);
                }
                mma_commit(sb + 64 + b * 8);
            }
        }
        if (elect1()) mma_commit(sb + 112);
    }

    mbar_wait(sb + 112, 0);
    tm_fence_after();

    {
        int sub = wid & 3, chalf = wid >> 2;
        int grow = tile * 128 + sub * 32 + lane;
        int tok = gRowTok[grow];
        float p = (tok >= 0) ? gP[tok] : 0.f;
        float* o = (tok >= 0) ? (out + (size_t)tok * DIMV + nb0 + chalf * 64) : nullptr;
#pragma unroll
        for (int pq = 0; pq < 2; pq++) {
            uint32_t r[32];
            ldtm32(r, tmem + chalf * 64 + pq * 32);
            tm_wait_ld();
            if (tok >= 0) {
#pragma unroll
                for (int j = 0; j < 32; j++)
                    o[pq * 32 + j] =
                        __bfloat162float(__float2bfloat16(__uint_as_float(r[j]))) * p;
            }
        }
    }
    __syncthreads();
    if (tid == 0) {
#pragma unroll
        for (int i = 0; i < 3; i++) { mbar_inval(sb + 16 + i * 8); mbar_inval(sb + 64 + i * 8); }
        mbar_inval(sb + 112);
    }
    __syncthreads();
    if (wid == 0) tmem_dealloc(tmem, 128);
#endif
}

// ------------------------- launcher ----------------------------------------
typedef CUresult (*EncodeFn)(CUtensorMap*, CUtensorMapDataType, cuuint32_t, void*,
                             const cuuint64_t*, const cuuint64_t*, const cuuint32_t*,
                             const cuuint32_t*, CUtensorMapInterleave, CUtensorMapSwizzle,
                             CUtensorMapL2promotion, CUtensorMapFloatOOBfill);

static void make_map(EncodeFn enc, CUtensorMap* m, void* base,
                     unsigned long long inner, unsigned long long outer) {
    cuuint64_t dims[2] = {inner, outer};
    cuuint64_t strides[1] = {inner * 2};
    cuuint32_t box[2] = {KC, 128};
    cuuint32_t es[2] = {1, 1};
    enc(m, CU_TENSOR_MAP_DATA_TYPE_BFLOAT16, 2, base, dims, strides, box, es,
        CU_TENSOR_MAP_INTERLEAVE_NONE, CU_TENSOR_MAP_SWIZZLE_64B,
        CU_TENSOR_MAP_L2_PROMOTION_L2_128B, CU_TENSOR_MAP_FLOAT_OOB_FILL_NONE);
}

extern "C" void kernel_launch(void* const* d_in, const int* in_sizes, int n_in,
                              void* d_out, int out_size) {
    const float* x  = (const float*)d_in[0];
    const float* rw = (const float*)d_in[1];
    const float* rb = (const float*)d_in[2];
    const float* w1 = (const float*)d_in[3];
    const float* w2 = (const float*)d_in[4];
    const float* w3 = (const float*)d_in[5];
    float* out = (float*)d_out;

    EncodeFn enc = nullptr;
    cudaDriverEntryPointQueryResult qr;
    cudaGetDriverEntryPoint("cuTensorMapEncodeTiled", (void**)&enc,
                            cudaEnableDefault, &qr);

    void *pXh, *pXl, *pW1h, *pW1l, *pW2h, *pW2l, *pUh, *pUl, *pW3h, *pW3l;
    cudaGetSymbolAddress(&pXh, gXh);   cudaGetSymbolAddress(&pXl, gXl);
    cudaGetSymbolAddress(&pW1h, gW1h); cudaGetSymbolAddress(&pW1l, gW1l);
    cudaGetSymbolAddress(&pW2h, gW2h); cudaGetSymbolAddress(&pW2l, gW2l);
    cudaGetSymbolAddress(&pUh, gUh);   cudaGetSymbolAddress(&pUl, gUl);
    cudaGetSymbolAddress(&pW3h, gW3h); cudaGetSymbolAddress(&pW3l, gW3l);

    CUtensorMap mXh, mXl, mW1h, mW1l, mW2h, mW2l, mUh, mUl, mW3h, mW3l;
    make_map(enc, &mXh, pXh, DIMV, MAXROWS);
    make_map(enc, &mXl, pXl, DIMV, MAXROWS);
    make_map(enc, &mW1h, pW1h, DIMV, (unsigned long long)NEXP * HIDV);
    make_map(enc, &mW1l, pW1l, DIMV, (unsigned long long)NEXP * HIDV);
    make_map(enc, &mW2h, pW2h, DIMV, (unsigned long long)NEXP * HIDV);
    make_map(enc, &mW2l, pW2l, DIMV, (unsigned long long)NEXP * HIDV);
    make_map(enc, &mUh, pUh, HIDV, MAXROWS);
    make_map(enc, &mUl, pUl, HIDV, MAXROWS);
    make_map(enc, &mW3h, pW3h, HIDV, (unsigned long long)NEXP * DIMV);
    make_map(enc, &mW3l, pW3l, HIDV, (unsigned long long)NEXP * DIMV);

    cudaFuncSetAttribute(gemm1_tc, cudaFuncAttributeMaxDynamicSharedMemorySize, G1_SMEM);
    cudaFuncSetAttribute(gemm2_tc, cudaFuncAttributeMaxDynamicSharedMemorySize, G2_SMEM);

    tsplit_all_k<<<dim3(32, 32, 24), 256>>>(w1, w2, w3);                 // 0
    routerplan_k<<<512, 256>>>(x, rw, rb);                               // 1
    gather_k<<<MAXROWS, 256>>>(x);                                       // 2
    gemm1_tc<<<dim3(HIDV / 128, NTILE), 256, G1_SMEM>>>(                 // 3 (profiled)
        mXh, mXl, mW1h, mW1l, mW2h, mW2l);
    gemm2_tc<<<dim3(DIMV / 128, NTILE), 256, G2_SMEM>>>(                 // 4
        out, mUh, mUl, mW3h, mW3l);
}

// round 12
// speedup vs baseline: 1.0583x; 1.0583x over previous
#include <cuda_runtime.h>
#include <cuda.h>
#include <cuda_bf16.h>
#include <cstdint>

typedef __nv_bfloat16 bf16;

#if defined(__CUDA_ARCH__) && (__CUDA_ARCH__ == 1030) && \
    (defined(__CUDA_ARCH_FEAT_SM103_ALL) || defined(__CUDA_ARCH_FEAT_SM100_ALL))
#define TC_OK 1
#else
#define TC_OK 0
#endif

#define DIMV 768
#define HIDV 2048
#define TOKV 4096
#define NEXP 8
#define MAXGRP 24
#define NTILE (MAXGRP*2)      // 48 row-tiles of 128
#define MAXROWS (MAXGRP*256)
#define KC 32                 // stage K elems (64B rows, SW64)

// ------------------------- device scratch ---------------------------------
__device__ bf16 gW1h[(size_t)NEXP*HIDV*DIMV];
__device__ bf16 gW1l[(size_t)NEXP*HIDV*DIMV];
__device__ bf16 gW2h[(size_t)NEXP*HIDV*DIMV];
__device__ bf16 gW2l[(size_t)NEXP*HIDV*DIMV];
__device__ bf16 gW3h[(size_t)NEXP*DIMV*HIDV];
__device__ bf16 gW3l[(size_t)NEXP*DIMV*HIDV];
__device__ bf16 gXh[(size_t)MAXROWS*DIMV];
__device__ bf16 gXl[(size_t)MAXROWS*DIMV];
__device__ bf16 gUh[(size_t)MAXROWS*HIDV];
__device__ bf16 gUl[(size_t)MAXROWS*HIDV];
__device__ int   gTokE[TOKV];
__device__ float gP[TOKV];
__device__ int   gRowTok[MAXROWS];
__device__ int   gGrpE[MAXGRP];
__device__ int   gDone;

// ------------------------- common helpers ----------------------------------
__device__ __forceinline__ uint32_t smem_u32(const void* p) {
    uint32_t a;
    asm("{ .reg .u64 t; cvta.to.shared.u64 t, %1; cvt.u32.u64 %0, t; }" : "=r"(a) : "l"(p));
    return a;
}
__device__ __forceinline__ void split2(float v, bf16& h, bf16& l) {
    h = __float2bfloat16(v);
    l = __float2bfloat16(v - __bfloat162float(h));
}

// ------------------------- tcgen05 / TMA helpers ---------------------------
__device__ __forceinline__ uint32_t elect1() {
    uint32_t p = 0;
#if TC_OK
    asm volatile("{ .reg .pred p; elect.sync _|p, 0xFFFFFFFF; selp.b32 %0,1,0,p; }" : "=r"(p));
#endif
    return p;
}
__device__ __forceinline__ uint64_t desc64(uint32_t addr) {
    // SW64: layout=4, version=1, SBO=32 (512B), LBO=1 (16B) — validated R5
    const uint64_t base = (uint64_t(4) << 61) | (uint64_t(1) << 46)
                        | (uint64_t(32) << 32) | (uint64_t(1) << 16);
    return base | ((uint64_t)(addr >> 4) & 0x3FFF);
}
#define IDESC 0x8200490u   // kind::f16, bf16 x bf16 -> f32, M=128, N=128

__device__ __forceinline__ void mma_ss(uint32_t d, uint64_t ad, uint64_t bd, uint32_t en) {
#if TC_OK
    asm volatile(
        "{\n .reg .pred p;\n setp.ne.u32 p, %4, 0;\n"
        " tcgen05.mma.cta_group::1.kind::f16 [%0], %1, %2, %3, {%5,%5,%5,%5}, p;\n}"
        :: "r"(d), "l"(ad), "l"(bd), "r"(IDESC), "r"(en), "r"(0u) : "memory");
#endif
}
__device__ __forceinline__ void mma_commit(uint32_t mbar) {
#if TC_OK
    asm volatile(
        "tcgen05.commit.cta_group::1.mbarrier::arrive::one.shared::cluster.b64 [%0];"
        :: "r"(mbar) : "memory");
#endif
}
__device__ __forceinline__ void tma2d(uint32_t smem, const CUtensorMap* map,
                                      int x, int y, uint32_t mbar) {
#if TC_OK
    asm volatile(
        "cp.async.bulk.tensor.2d.shared::cta.global.tile.mbarrier::complete_tx::bytes "
        "[%0], [%1, {%2, %3}], [%4];"
        :: "r"(smem), "l"(map), "r"(x), "r"(y), "r"(mbar) : "memory");
#endif
}
__device__ __forceinline__ void expect_tx(uint32_t mbar, uint32_t bytes) {
#if TC_OK
    asm volatile("mbarrier.arrive.expect_tx.shared.b64 _, [%0], %1;"
                 :: "r"(mbar), "r"(bytes) : "memory");
#endif
}
__device__ __forceinline__ void mbar_init(uint32_t a, uint32_t c) {
#if TC_OK
    asm volatile("mbarrier.init.shared.b64 [%0], %1;" :: "r"(a), "r"(c) : "memory");
#endif
}
__device__ __forceinline__ void mbar_inval(uint32_t a) {
#if TC_OK
    asm volatile("mbarrier.inval.shared.b64 [%0];" :: "r"(a) : "memory");
#endif
}
__device__ __forceinline__ void mbar_wait(uint32_t a, uint32_t ph) {
#if TC_OK
    uint32_t ok = 0;
    while (!ok) {
        asm volatile(
            "{\n .reg .pred P;\n"
            " mbarrier.try_wait.parity.acquire.cta.shared::cta.b64 P, [%1], %2, 0x989680;\n"
            " selp.b32 %0, 1, 0, P;\n}"
            : "=r"(ok) : "r"(a), "r"(ph) : "memory");
    }
#endif
}
// alloc + IMMEDIATE permit relinquish: holding the permit for the kernel's
// lifetime blocks the co-resident CTA inside tcgen05.alloc (R11 regression).
__device__ __forceinline__ void tmem_alloc_release(uint32_t smem_ptr, uint32_t ncols) {
#if TC_OK
    asm volatile("tcgen05.alloc.cta_group::1.sync.aligned.shared::cta.b32 [%0], %1;"
                 :: "r"(smem_ptr), "r"(ncols) : "memory");
    asm volatile("tcgen05.relinquish_alloc_permit.cta_group::1.sync.aligned;");
#endif
}
__device__ __forceinline__ void tmem_dealloc(uint32_t tmem, uint32_t ncols) {
#if TC_OK
    asm volatile("tcgen05.dealloc.cta_group::1.sync.aligned.b32 %0, %1;" :: "r"(tmem), "r"(ncols));
#endif
}
__device__ __forceinline__ void ldtm32(uint32_t* r, uint32_t ta) {
#if TC_OK
    asm volatile(
        "tcgen05.ld.sync.aligned.32x32b.x32.b32 "
        "{%0,%1,%2,%3,%4,%5,%6,%7,%8,%9,%10,%11,%12,%13,%14,%15,"
        "%16,%17,%18,%19,%20,%21,%22,%23,%24,%25,%26,%27,%28,%29,%30,%31}, [%32];"
        : "=r"(r[0]), "=r"(r[1]), "=r"(r[2]), "=r"(r[3]), "=r"(r[4]), "=r"(r[5]),
          "=r"(r[6]), "=r"(r[7]), "=r"(r[8]), "=r"(r[9]), "=r"(r[10]), "=r"(r[11]),
          "=r"(r[12]), "=r"(r[13]), "=r"(r[14]), "=r"(r[15]), "=r"(r[16]), "=r"(r[17]),
          "=r"(r[18]), "=r"(r[19]), "=r"(r[20]), "=r"(r[21]), "=r"(r[22]), "=r"(r[23]),
          "=r"(r[24]), "=r"(r[25]), "=r"(r[26]), "=r"(r[27]), "=r"(r[28]), "=r"(r[29]),
          "=r"(r[30]), "=r"(r[31])
        : "r"(ta));
#endif
}
__device__ __forceinline__ void tm_wait_ld() {
#if TC_OK
    asm volatile("tcgen05.wait::ld.sync.aligned;" ::: "memory");
#endif
}
__device__ __forceinline__ void tm_fence_after() {
#if TC_OK
    asm volatile("tcgen05.fence::after_thread_sync;" ::: "memory");
#endif
}

// ================= launch 0: all weight transposes + split =================
__global__ void tsplit_all_k(const float* __restrict__ w1,
                             const float* __restrict__ w2,
                             const float* __restrict__ w3) {
    __shared__ float tile[64][65];
    int z = blockIdx.z;
    if (z == 0 && blockIdx.x == 0 && blockIdx.y == 0 && threadIdx.x == 0) gDone = 0;
    int R, C, e;
    const float* src;
    bf16 *dh, *dl;
    if (z < 16) {
        R = DIMV; C = HIDV; e = z & 7;
        src = (z < 8) ? w1 : w2;
        dh = (z < 8) ? gW1h : gW2h;
        dl = (z < 8) ? gW1l : gW2l;
        if ((int)blockIdx.y >= R / 64) return;
    } else {
        R = HIDV; C = DIMV; e = z - 16;
        src = w3; dh = gW3h; dl = gW3l;
        if ((int)blockIdx.x >= C / 64) return;
    }
    int c0 = blockIdx.x * 64, r0 = blockIdx.y * 64;
    int tid = threadIdx.x;
    const float* s = src + (size_t)e * R * C;
#pragma unroll
    for (int i = 0; i < 16; i++) {
        int idx = i * 256 + tid;
        int r = idx >> 6, c = idx & 63;
        tile[r][c] = s[(size_t)(r0 + r) * C + c0 + c];
    }
    __syncthreads();
    bf16* dhp = dh + (size_t)e * C * R;
    bf16* dlp = dl + (size_t)e * C * R;
#pragma unroll
    for (int i = 0; i < 8; i++) {
        int idx = i * 256 + tid;
        int c = idx >> 5, rp = idx & 31, r = rp * 2;
        float v0 = tile[r][c], v1 = tile[r + 1][c];
        bf16 h0, l0, h1, l1;
        split2(v0, h0, l0);
        split2(v1, h1, l1);
        __nv_bfloat162 vh; vh.x = h0; vh.y = h1;
        __nv_bfloat162 vl; vl.x = l0; vl.y = l1;
        size_t o = (size_t)(c0 + c) * R + r0 + r;
        *(__nv_bfloat162*)(dhp + o) = vh;
        *(__nv_bfloat162*)(dlp + o) = vl;
    }
}

// ========== launch 1: router + (last block) plan ===========================
__global__ void routerplan_k(const float* __restrict__ x,
                             const float* __restrict__ rw,
                             const float* __restrict__ rb) {
    int tid = threadIdx.x;
    int warp = tid >> 5, lane = tid & 31;
    int tok = blockIdx.x * 8 + warp;
    {
        const float* xr = x + (size_t)tok * DIMV;
        float acc[NEXP];
#pragma unroll
        for (int e = 0; e < NEXP; e++) acc[e] = 0.f;
        for (int k = lane; k < DIMV; k += 32) {
            float xv = xr[k];
            const float* w = rw + k * NEXP;
#pragma unroll
            for (int e = 0; e < NEXP; e++) acc[e] += xv * w[e];
        }
#pragma unroll
        for (int off = 16; off; off >>= 1)
#pragma unroll
            for (int e = 0; e < NEXP; e++)
                acc[e] += __shfl_xor_sync(0xffffffffu, acc[e], off);
        if (lane == 0) {
            float l[NEXP];
            float m = -1e30f; int mi = 0;
#pragma unroll
            for (int e = 0; e < NEXP; e++) {
                l[e] = acc[e] + rb[e];
                if (l[e] > m) { m = l[e]; mi = e; }
            }
            float s = 0.f;
#pragma unroll
            for (int e = 0; e < NEXP; e++) s += expf(l[e] - m);
            gTokE[tok] = mi;
            gP[tok] = 1.f / s;
        }
    }
    __shared__ int sLast;
    __threadfence();
    __syncthreads();
    if (tid == 0) {
        int v = atomicAdd(&gDone, 1);
        sLast = (v == (int)gridDim.x - 1) ? 1 : 0;
    }
    __syncthreads();
    if (!sLast) return;

    __shared__ int cnt[NEXP], cur[NEXP], base[NEXP];
    if (tid < NEXP) { cnt[tid] = 0; cur[tid] = 0; }
    __syncthreads();
    for (int t = tid; t < TOKV; t += 256) atomicAdd(&cnt[gTokE[t]], 1);
    __syncthreads();
    if (tid == 0) {
        int acc = 0, gc = 0;
        for (int e = 0; e < NEXP; e++) {
            base[e] = acc;
            int ng = (cnt[e] + 255) >> 8;
            for (int i = 0; i < ng && gc < MAXGRP; i++) gGrpE[gc++] = e;
            acc += ng * 256;
        }
        for (; gc < MAXGRP; gc++) gGrpE[gc] = 0;
    }
    __syncthreads();
    for (int r = tid; r < MAXROWS; r += 256) gRowTok[r] = -1;
    __syncthreads();
    for (int t = tid; t < TOKV; t += 256) {
        int e = gTokE[t];
        int s = atomicAdd(&cur[e], 1);
        gRowTok[base[e] + s] = t;
    }
}

// ================= launch 2: gather X + split ==============================
__global__ void gather_k(const float* __restrict__ x) {
    int row = blockIdx.x;
    int tok = gRowTok[row];
    for (int k = threadIdx.x; k < DIMV; k += blockDim.x) {
        float v = (tok >= 0) ? x[(size_t)tok * DIMV + k] : 0.f;
        bf16 h, l; split2(v, h, l);
        gXh[(size_t)row * DIMV + k] = h;
        gXl[(size_t)row * DIMV + k] = l;
    }
}

// ========= GEMM1: M=128/CTA, TMA warp-specialized, depth 2, 2 CTA/SM =======
// smem: [0] tmem ptr, full[2]@16, empty[2]@64, done@112
// stage (48KB): Ah Al (8KB) B1h B1l B2h B2l (8KB each)
#define G1_STG 49152
#define G1_SMEM (1024 + 2*G1_STG)

__global__ __launch_bounds__(256) void gemm1_tc(
    const __grid_constant__ CUtensorMap mXh, const __grid_constant__ CUtensorMap mXl,
    const __grid_constant__ CUtensorMap mW1h, const __grid_constant__ CUtensorMap mW1l,
    const __grid_constant__ CUtensorMap mW2h, const __grid_constant__ CUtensorMap mW2l) {
#if TC_OK
    extern __shared__ char smem[];
    uint32_t sb = smem_u32(smem);
    int tid = threadIdx.x, wid = tid >> 5, lane = tid & 31;
    int tile = blockIdx.y, nb0 = blockIdx.x * 128;
    int e = gGrpE[tile >> 1];

    if (wid == 0) tmem_alloc_release(sb, 256);
    if (tid == 0) {
#pragma unroll
        for (int i = 0; i < 2; i++) {
            mbar_init(sb + 16 + i * 8, 1);  // full
            mbar_init(sb + 64 + i * 8, 1);  // empty
        }
        mbar_init(sb + 112, 1);             // done
    }
    __syncthreads();
    uint32_t tmem;
    asm volatile("ld.shared.b32 %0, [%1];" : "=r"(tmem) : "r"(sb));

    const int NS = DIMV / KC;  // 24
    if (wid == 0 && elect1()) {             // producer
        int aY = tile * 128, bY = e * HIDV + nb0;
        for (int s = 0; s < NS; s++) {
            int b = s & 1;
            if (s >= 2) mbar_wait(sb + 64 + b * 8, (uint32_t)(((s - 2) >> 1) & 1));
            uint32_t st = sb + 1024 + b * G1_STG;
            uint32_t fb = sb + 16 + b * 8;
            int kc = s * KC;
            expect_tx(fb, 49152);
            tma2d(st,         &mXh,  kc, aY, fb);
            tma2d(st + 8192,  &mXl,  kc, aY, fb);
            tma2d(st + 16384, &mW1h, kc, bY, fb);
            tma2d(st + 24576, &mW1l, kc, bY, fb);
            tma2d(st + 32768, &mW2h, kc, bY, fb);
            tma2d(st + 40960, &mW2l, kc, bY, fb);
        }
    }
    if (wid == 1) {                          // consumer (MMA)
        for (int s = 0; s < NS; s++) {
            int b = s & 1;
            mbar_wait(sb + 16 + b * 8, (uint32_t)((s >> 1) & 1));
            if (elect1()) {
                uint32_t st = sb + 1024 + b * G1_STG;
                uint64_t ah = desc64(st), al = desc64(st + 8192);
                uint64_t b1h = desc64(st + 16384), b1l = desc64(st + 24576);
                uint64_t b2h = desc64(st + 32768), b2l = desc64(st + 40960);
                uint32_t D1 = tmem, D2 = tmem + 128;
#pragma unroll
                for (int k = 0; k < 2; k++) {
                    uint32_t en = (s == 0 && k == 0) ? 0u : 1u;
                    uint64_t k2 = (uint64_t)(k * 2);
                    mma_ss(D1, ah + k2, b1h + k2, en);
                    mma_ss(D1, ah + k2, b1l + k2, 1u);
                    mma_ss(D1, al + k2, b1h + k2, 1u);
                    mma_ss(D2, ah + k2, b2h + k2, en);
                    mma_ss(D2, ah + k2, b2l + k2, 1u);
                    mma_ss(D2, al + k2, b2h + k2, 1u);
                }
                mma_commit(sb + 64 + b * 8);
            }
        }
        if (elect1()) mma_commit(sb + 112);
    }

    mbar_wait(sb + 112, 0);
    tm_fence_after();

    {
        int sub = wid & 3, chalf = wid >> 2;
        int grow = tile * 128 + sub * 32 + lane;
        bf16* dh = gUh + (size_t)grow * HIDV + nb0 + chalf * 64;
        bf16* dl = gUl + (size_t)grow * HIDV + nb0 + chalf * 64;
#pragma unroll
        for (int p = 0; p < 2; p++) {
            uint32_t r1[32], r2[32];
            ldtm32(r1, tmem + chalf * 64 + p * 32);
            ldtm32(r2, tmem + 128 + chalf * 64 + p * 32);
            tm_wait_ld();
#pragma unroll
            for (int j = 0; j < 32; j += 2) {
                float h1a = __uint_as_float(r1[j]),     h2a = __uint_as_float(r2[j]);
                float h1b = __uint_as_float(r1[j + 1]), h2b = __uint_as_float(r2[j + 1]);
                float ua = h1a * (1.f / (1.f + expf(-h1a))) * h2a;
                float ub = h1b * (1.f / (1.f + expf(-h1b))) * h2b;
                bf16 ha, la, hb, lb;
                split2(ua, ha, la);
                split2(ub, hb, lb);
                __nv_bfloat162 vh; vh.x = ha; vh.y = hb;
                __nv_bfloat162 vl; vl.x = la; vl.y = lb;
                *(__nv_bfloat162*)(dh + p * 32 + j) = vh;
                *(__nv_bfloat162*)(dl + p * 32 + j) = vl;
            }
        }
    }
    __syncthreads();
    if (tid == 0) {
#pragma unroll
        for (int i = 0; i < 2; i++) { mbar_inval(sb + 16 + i * 8); mbar_inval(sb + 64 + i * 8); }
        mbar_inval(sb + 112);
    }
    __syncthreads();
    if (wid == 0) tmem_dealloc(tmem, 256);
#endif
}

// ========= GEMM2: M=128/CTA, TMA warp-specialized, depth 3, 2 CTA/SM =======
// stage (32KB): Ah Al Bh Bl (8KB each)
#define G2_STG 32768
#define G2_SMEM (1024 + 3*G2_STG)

__global__ __launch_bounds__(256) void gemm2_tc(
    float* __restrict__ out,
    const __grid_constant__ CUtensorMap mUh, const __grid_constant__ CUtensorMap mUl,
    const __grid_constant__ CUtensorMap mW3h, const __grid_constant__ CUtensorMap mW3l) {
#if TC_OK
    extern __shared__ char smem[];
    uint32_t sb = smem_u32(smem);
    int tid = threadIdx.x, wid = tid >> 5, lane = tid & 31;
    int tile = blockIdx.y, nb0 = blockIdx.x * 128;
    int e = gGrpE[tile >> 1];

    if (wid == 0) tmem_alloc_release(sb, 128);
    if (tid == 0) {
#pragma unroll
        for (int i = 0; i < 3; i++) {
            mbar_init(sb + 16 + i * 8, 1);
            mbar_init(sb + 64 + i * 8, 1);
        }
        mbar_init(sb + 112, 1);
    }
    __syncthreads();
    uint32_t tmem;
    asm volatile("ld.shared.b32 %0, [%1];" : "=r"(tmem) : "r"(sb));

    const int NS = HIDV / KC;  // 64
    if (wid == 0 && elect1()) {
        int aY = tile * 128, bY = e * DIMV + nb0;
        for (int s = 0; s < NS; s++) {
            int b = s % 3;
            if (s >= 3) mbar_wait(sb + 64 + b * 8, (uint32_t)(((s - 3) / 3) & 1));
            uint32_t st = sb + 1024 + b * G2_STG;
            uint32_t fb = sb + 16 + b * 8;
            int kc = s * KC;
            expect_tx(fb, 32768);
            tma2d(st,         &mUh,  kc, aY, fb);
            tma2d(st + 8192,  &mUl,  kc, aY, fb);
            tma2d(st + 16384, &mW3h, kc, bY, fb);
            tma2d(st + 24576, &mW3l, kc, bY, fb);
        }
    }
    if (wid == 1) {
        for (int s = 0; s < NS; s++) {
            int b = s % 3;
            mbar_wait(sb + 16 + b * 8, (uint32_t)((s / 3) & 1));
            if (elect1()) {
                uint32_t st = sb + 1024 + b * G2_STG;
                uint64_t ah = desc64(st), al = desc64(st + 8192);
                uint64_t bh = desc64(st + 16384), bl = desc64(st + 24576);
#pragma unroll
                for (int k = 0; k < 2; k++) {
                    uint32_t en = (s == 0 && k == 0) ? 0u : 1u;
                    uint64_t k2 = (uint64_t)(k * 2);
                    mma_ss(tmem, ah + k2, bh + k2, en);
                    mma_ss(tmem, ah + k2, bl + k2, 1u);
                    mma_ss(tmem, al + k2, bh + k2, 1u);
                }
                mma_commit(sb + 64 + b * 8);
            }
        }
        if (elect1()) mma_commit(sb + 112);
    }

    mbar_wait(sb + 112, 0);
    tm_fence_after();

    {
        int sub = wid & 3, chalf = wid >> 2;
        int grow = tile * 128 + sub * 32 + lane;
        int tok = gRowTok[grow];
        float p = (tok >= 0) ? gP[tok] : 0.f;
        float* o = (tok >= 0) ? (out + (size_t)tok * DIMV + nb0 + chalf * 64) : nullptr;
#pragma unroll
        for (int pq = 0; pq < 2; pq++) {
            uint32_t r[32];
            ldtm32(r, tmem + chalf * 64 + pq * 32);
            tm_wait_ld();
            if (tok >= 0) {
#pragma unroll
                for (int j = 0; j < 32; j++)
                    o[pq * 32 + j] =
                        __bfloat162float(__float2bfloat16(__uint_as_float(r[j]))) * p;
            }
        }
    }
    __syncthreads();
    if (tid == 0) {
#pragma unroll
        for (int i = 0; i < 3; i++) { mbar_inval(sb + 16 + i * 8); mbar_inval(sb + 64 + i * 8); }
        mbar_inval(sb + 112);
    }
    __syncthreads();
    if (wid == 0) tmem_dealloc(tmem, 128);
#endif
}

// ------------------------- launcher ----------------------------------------
typedef CUresult (*EncodeFn)(CUtensorMap*, CUtensorMapDataType, cuuint32_t, void*,
                             const cuuint64_t*, const cuuint64_t*, const cuuint32_t*,
                             const cuuint32_t*, CUtensorMapInterleave, CUtensorMapSwizzle,
                             CUtensorMapL2promotion, CUtensorMapFloatOOBfill);

static void make_map(EncodeFn enc, CUtensorMap* m, void* base,
                     unsigned long long inner, unsigned long long outer) {
    cuuint64_t dims[2] = {inner, outer};
    cuuint64_t strides[1] = {inner * 2};
    cuuint32_t box[2] = {KC, 128};
    cuuint32_t es[2] = {1, 1};
    enc(m, CU_TENSOR_MAP_DATA_TYPE_BFLOAT16, 2, base, dims, strides, box, es,
        CU_TENSOR_MAP_INTERLEAVE_NONE, CU_TENSOR_MAP_SWIZZLE_64B,
        CU_TENSOR_MAP_L2_PROMOTION_L2_128B, CU_TENSOR_MAP_FLOAT_OOB_FILL_NONE);
}

extern "C" void kernel_launch(void* const* d_in, const int* in_sizes, int n_in,
                              void* d_out, int out_size) {
    const float* x  = (const float*)d_in[0];
    const float* rw = (const float*)d_in[1];
    const float* rb = (const float*)d_in[2];
    const float* w1 = (const float*)d_in[3];
    const float* w2 = (const float*)d_in[4];
    const float* w3 = (const float*)d_in[5];
    float* out = (float*)d_out;

    EncodeFn enc = nullptr;
    cudaDriverEntryPointQueryResult qr;
    cudaGetDriverEntryPoint("cuTensorMapEncodeTiled", (void**)&enc,
                            cudaEnableDefault, &qr);

    void *pXh, *pXl, *pW1h, *pW1l, *pW2h, *pW2l, *pUh, *pUl, *pW3h, *pW3l;
    cudaGetSymbolAddress(&pXh, gXh);   cudaGetSymbolAddress(&pXl, gXl);
    cudaGetSymbolAddress(&pW1h, gW1h); cudaGetSymbolAddress(&pW1l, gW1l);
    cudaGetSymbolAddress(&pW2h, gW2h); cudaGetSymbolAddress(&pW2l, gW2l);
    cudaGetSymbolAddress(&pUh, gUh);   cudaGetSymbolAddress(&pUl, gUl);
    cudaGetSymbolAddress(&pW3h, gW3h); cudaGetSymbolAddress(&pW3l, gW3l);

    CUtensorMap mXh, mXl, mW1h, mW1l, mW2h, mW2l, mUh, mUl, mW3h, mW3l;
    make_map(enc, &mXh, pXh, DIMV, MAXROWS);
    make_map(enc, &mXl, pXl, DIMV, MAXROWS);
    make_map(enc, &mW1h, pW1h, DIMV, (unsigned long long)NEXP * HIDV);
    make_map(enc, &mW1l, pW1l, DIMV, (unsigned long long)NEXP * HIDV);
    make_map(enc, &mW2h, pW2h, DIMV, (unsigned long long)NEXP * HIDV);
    make_map(enc, &mW2l, pW2l, DIMV, (unsigned long long)NEXP * HIDV);
    make_map(enc, &mUh, pUh, HIDV, MAXROWS);
    make_map(enc, &mUl, pUl, HIDV, MAXROWS);
    make_map(enc, &mW3h, pW3h, HIDV, (unsigned long long)NEXP * DIMV);
    make_map(enc, &mW3l, pW3l, HIDV, (unsigned long long)NEXP * DIMV);

    cudaFuncSetAttribute(gemm1_tc, cudaFuncAttributeMaxDynamicSharedMemorySize, G1_SMEM);
    cudaFuncSetAttribute(gemm2_tc, cudaFuncAttributeMaxDynamicSharedMemorySize, G2_SMEM);

    tsplit_all_k<<<dim3(32, 32, 24), 256>>>(w1, w2, w3);                 // 0
    routerplan_k<<<512, 256>>>(x, rw, rb);                               // 1
    gather_k<<<MAXROWS, 256>>>(x);                                       // 2
    gemm1_tc<<<dim3(HIDV / 128, NTILE), 256, G1_SMEM>>>(                 // 3 (profiled)
        mXh, mXl, mW1h, mW1l, mW2h, mW2l);
    gemm2_tc<<<dim3(DIMV / 128, NTILE), 256, G2_SMEM>>>(                 // 4
        out, mUh, mUl, mW3h, mW3l);
}

// round 13
// speedup vs baseline: 1.1791x; 1.1141x over previous
#include <cuda_runtime.h>
#include <cuda_bf16.h>
#include <cstdint>

typedef __nv_bfloat16 bf16;

#if defined(__CUDA_ARCH__) && (__CUDA_ARCH__ == 1030) && \
    (defined(__CUDA_ARCH_FEAT_SM103_ALL) || defined(__CUDA_ARCH_FEAT_SM100_ALL))
#define TC_OK 1
#else
#define TC_OK 0
#endif

#define DIMV 768
#define HIDV 2048
#define TOKV 4096
#define NEXP 8
#define MAXGRP 24
#define NTILE (MAXGRP*2)      // 48 row-tiles of 128
#define MAXROWS (MAXGRP*256)
#define KC 32                 // stage K elems -> 8KB blocks (128 x 64B, SW64)
#define NCH1 (DIMV/KC)        // 24 k-chunks (X, W1, W2)
#define NCH2 (HIDV/KC)        // 64 k-chunks (U, W3)
#define BLKB 8192             // bytes per block

// ------------------------- device scratch (blocked, pre-swizzled) ----------
// W1/W2: [e][n_tile 16][k_chunk 24][8KB]   W3: [e][n_tile 6][k_chunk 64][8KB]
// X: [tile 48][k_chunk 24][8KB]            U: [tile 48][k_chunk 64][8KB]
__device__ bf16 gW1h[(size_t)NEXP*HIDV*DIMV];
__device__ bf16 gW1l[(size_t)NEXP*HIDV*DIMV];
__device__ bf16 gW2h[(size_t)NEXP*HIDV*DIMV];
__device__ bf16 gW2l[(size_t)NEXP*HIDV*DIMV];
__device__ bf16 gW3h[(size_t)NEXP*DIMV*HIDV];
__device__ bf16 gW3l[(size_t)NEXP*DIMV*HIDV];
__device__ bf16 gXh[(size_t)MAXROWS*DIMV];
__device__ bf16 gXl[(size_t)MAXROWS*DIMV];
__device__ bf16 gUh[(size_t)MAXROWS*HIDV];
__device__ bf16 gUl[(size_t)MAXROWS*HIDV];
__device__ int   gTokE[TOKV];
__device__ float gP[TOKV];
__device__ int   gRowTok[MAXROWS];
__device__ int   gGrpE[MAXGRP];
__device__ int   gDone;

// ------------------------- common helpers ----------------------------------
__device__ __forceinline__ uint32_t smem_u32(const void* p) {
    uint32_t a;
    asm("{ .reg .u64 t; cvta.to.shared.u64 t, %1; cvt.u32.u64 %0, t; }" : "=r"(a) : "l"(p));
    return a;
}
__device__ __forceinline__ void split2(float v, bf16& h, bf16& l) {
    h = __float2bfloat16(v);
    l = __float2bfloat16(v - __bfloat162float(h));
}
#define SWZ64(x) ((x) ^ (((x) >> 3) & 0x30))

// ------------------------- tcgen05 / bulk-copy helpers ---------------------
__device__ __forceinline__ uint32_t elect1() {
    uint32_t p = 0;
#if TC_OK
    asm volatile("{ .reg .pred p; elect.sync _|p, 0xFFFFFFFF; selp.b32 %0,1,0,p; }" : "=r"(p));
#endif
    return p;
}
__device__ __forceinline__ uint64_t desc64(uint32_t addr) {
    // SW64: layout=4, version=1, SBO=32 (512B), LBO=1 (16B) — validated R5
    const uint64_t base = (uint64_t(4) << 61) | (uint64_t(1) << 46)
                        | (uint64_t(32) << 32) | (uint64_t(1) << 16);
    return base | ((uint64_t)(addr >> 4) & 0x3FFF);
}
#define IDESC 0x8200490u   // kind::f16, bf16 x bf16 -> f32, M=128, N=128

__device__ __forceinline__ void mma_ss(uint32_t d, uint64_t ad, uint64_t bd, uint32_t en) {
#if TC_OK
    asm volatile(
        "{\n .reg .pred p;\n setp.ne.u32 p, %4, 0;\n"
        " tcgen05.mma.cta_group::1.kind::f16 [%0], %1, %2, %3, {%5,%5,%5,%5}, p;\n}"
        :: "r"(d), "l"(ad), "l"(bd), "r"(IDESC), "r"(en), "r"(0u) : "memory");
#endif
}
__device__ __forceinline__ void mma_commit(uint32_t mbar) {
#if TC_OK
    asm volatile(
        "tcgen05.commit.cta_group::1.mbarrier::arrive::one.shared::cluster.b64 [%0];"
        :: "r"(mbar) : "memory");
#endif
}
// contiguous 1D bulk copy GMEM->SMEM (UBLKCP), complete_tx on mbar
__device__ __forceinline__ void blkcp(uint32_t dst, const void* src, uint32_t bytes,
                                      uint32_t mbar) {
#if TC_OK
    asm volatile(
        "cp.async.bulk.shared::cluster.global.mbarrier::complete_tx::bytes "
        "[%0], [%1], %2, [%3];"
        :: "r"(dst), "l"(src), "r"(bytes), "r"(mbar) : "memory");
#endif
}
__device__ __forceinline__ void expect_tx(uint32_t mbar, uint32_t bytes) {
#if TC_OK
    asm volatile("mbarrier.arrive.expect_tx.shared.b64 _, [%0], %1;"
                 :: "r"(mbar), "r"(bytes) : "memory");
#endif
}
__device__ __forceinline__ void mbar_init(uint32_t a, uint32_t c) {
#if TC_OK
    asm volatile("mbarrier.init.shared.b64 [%0], %1;" :: "r"(a), "r"(c) : "memory");
#endif
}
__device__ __forceinline__ void mbar_inval(uint32_t a) {
#if TC_OK
    asm volatile("mbarrier.inval.shared.b64 [%0];" :: "r"(a) : "memory");
#endif
}
__device__ __forceinline__ void mbar_wait(uint32_t a, uint32_t ph) {
#if TC_OK
    uint32_t ok = 0;
    while (!ok) {
        asm volatile(
            "{\n .reg .pred P;\n"
            " mbarrier.try_wait.parity.acquire.cta.shared::cta.b64 P, [%1], %2, 0x989680;\n"
            " selp.b32 %0, 1, 0, P;\n}"
            : "=r"(ok) : "r"(a), "r"(ph) : "memory");
    }
#endif
}
// alloc + IMMEDIATE permit relinquish (R12 fix: keeps 2nd CTA from blocking)
__device__ __forceinline__ void tmem_alloc_release(uint32_t smem_ptr, uint32_t ncols) {
#if TC_OK
    asm volatile("tcgen05.alloc.cta_group::1.sync.aligned.shared::cta.b32 [%0], %1;"
                 :: "r"(smem_ptr), "r"(ncols) : "memory");
    asm volatile("tcgen05.relinquish_alloc_permit.cta_group::1.sync.aligned;");
#endif
}
__device__ __forceinline__ void tmem_dealloc(uint32_t tmem, uint32_t ncols) {
#if TC_OK
    asm volatile("tcgen05.dealloc.cta_group::1.sync.aligned.b32 %0, %1;" :: "r"(tmem), "r"(ncols));
#endif
}
__device__ __forceinline__ void ldtm32(uint32_t* r, uint32_t ta) {
#if TC_OK
    asm volatile(
        "tcgen05.ld.sync.aligned.32x32b.x32.b32 "
        "{%0,%1,%2,%3,%4,%5,%6,%7,%8,%9,%10,%11,%12,%13,%14,%15,"
        "%16,%17,%18,%19,%20,%21,%22,%23,%24,%25,%26,%27,%28,%29,%30,%31}, [%32];"
        : "=r"(r[0]), "=r"(r[1]), "=r"(r[2]), "=r"(r[3]), "=r"(r[4]), "=r"(r[5]),
          "=r"(r[6]), "=r"(r[7]), "=r"(r[8]), "=r"(r[9]), "=r"(r[10]), "=r"(r[11]),
          "=r"(r[12]), "=r"(r[13]), "=r"(r[14]), "=r"(r[15]), "=r"(r[16]), "=r"(r[17]),
          "=r"(r[18]), "=r"(r[19]), "=r"(r[20]), "=r"(r[21]), "=r"(r[22]), "=r"(r[23]),
          "=r"(r[24]), "=r"(r[25]), "=r"(r[26]), "=r"(r[27]), "=r"(r[28]), "=r"(r[29]),
          "=r"(r[30]), "=r"(r[31])
        : "r"(ta));
#endif
}
__device__ __forceinline__ void tm_wait_ld() {
#if TC_OK
    asm volatile("tcgen05.wait::ld.sync.aligned;" ::: "memory");
#endif
}
__device__ __forceinline__ void tm_fence_after() {
#if TC_OK
    asm volatile("tcgen05.fence::after_thread_sync;" ::: "memory");
#endif
}

// ================= launch 0: weight transpose + split -> blocked/swizzled ==
__global__ void tsplit_all_k(const float* __restrict__ w1,
                             const float* __restrict__ w2,
                             const float* __restrict__ w3) {
    __shared__ float tile[64][65];
    int z = blockIdx.z;
    if (z == 0 && blockIdx.x == 0 && blockIdx.y == 0 && threadIdx.x == 0) gDone = 0;
    int R, C, e;
    const float* src;
    char *dh, *dl;
    int ntile, nch;
    if (z < 16) {
        R = DIMV; C = HIDV; e = z & 7;
        src = (z < 8) ? w1 : w2;
        dh = (char*)((z < 8) ? gW1h : gW2h);
        dl = (char*)((z < 8) ? gW1l : gW2l);
        ntile = 16; nch = NCH1;
        if ((int)blockIdx.y >= R / 64) return;
    } else {
        R = HIDV; C = DIMV; e = z - 16;
        src = w3; dh = (char*)gW3h; dl = (char*)gW3l;
        ntile = 6; nch = NCH2;
        if ((int)blockIdx.x >= C / 64) return;
    }
    int c0 = blockIdx.x * 64, r0 = blockIdx.y * 64;
    int tid = threadIdx.x;
    const float* s = src + (size_t)e * R * C;
#pragma unroll
    for (int i = 0; i < 16; i++) {
        int idx = i * 256 + tid;
        int r = idx >> 6, c = idx & 63;
        tile[r][c] = s[(size_t)(r0 + r) * C + c0 + c];
    }
    __syncthreads();
#pragma unroll
    for (int i = 0; i < 8; i++) {
        int idx = i * 256 + tid;
        int c = idx >> 5, rp = idx & 31, r = rp * 2;
        float v0 = tile[r][c], v1 = tile[r + 1][c];
        bf16 h0, l0, h1, l1;
        split2(v0, h0, l0);
        split2(v1, h1, l1);
        __nv_bfloat162 vh; vh.x = h0; vh.y = h1;
        __nv_bfloat162 vl; vl.x = l0; vl.y = l1;
        int n = c0 + c;          // N-dim index (output row of blocked tile)
        int k = r0 + r;          // K-dim index
        size_t blk = ((size_t)(e * ntile + (n >> 7)) * nch + (k >> 5)) * BLKB;
        uint32_t off = SWZ64((uint32_t)((n & 127) * 64 + (k & 31) * 2));
        *(__nv_bfloat162*)(dh + blk + off) = vh;
        *(__nv_bfloat162*)(dl + blk + off) = vl;
    }
}

// ========== launch 1: router + (last block) plan ===========================
__global__ void routerplan_k(const float* __restrict__ x,
                             const float* __restrict__ rw,
                             const float* __restrict__ rb) {
    int tid = threadIdx.x;
    int warp = tid >> 5, lane = tid & 31;
    int tok = blockIdx.x * 8 + warp;
    {
        const float* xr = x + (size_t)tok * DIMV;
        float acc[NEXP];
#pragma unroll
        for (int e = 0; e < NEXP; e++) acc[e] = 0.f;
        for (int k = lane; k < DIMV; k += 32) {
            float xv = xr[k];
            const float* w = rw + k * NEXP;
#pragma unroll
            for (int e = 0; e < NEXP; e++) acc[e] += xv * w[e];
        }
#pragma unroll
        for (int off = 16; off; off >>= 1)
#pragma unroll
            for (int e = 0; e < NEXP; e++)
                acc[e] += __shfl_xor_sync(0xffffffffu, acc[e], off);
        if (lane == 0) {
            float l[NEXP];
            float m = -1e30f; int mi = 0;
#pragma unroll
            for (int e = 0; e < NEXP; e++) {
                l[e] = acc[e] + rb[e];
                if (l[e] > m) { m = l[e]; mi = e; }
            }
            float s = 0.f;
#pragma unroll
            for (int e = 0; e < NEXP; e++) s += expf(l[e] - m);
            gTokE[tok] = mi;
            gP[tok] = 1.f / s;
        }
    }
    __shared__ int sLast;
    __threadfence();
    __syncthreads();
    if (tid == 0) {
        int v = atomicAdd(&gDone, 1);
        sLast = (v == (int)gridDim.x - 1) ? 1 : 0;
    }
    __syncthreads();
    if (!sLast) return;

    __shared__ int cnt[NEXP], cur[NEXP], base[NEXP];
    if (tid < NEXP) { cnt[tid] = 0; cur[tid] = 0; }
    __syncthreads();
    for (int t = tid; t < TOKV; t += 256) atomicAdd(&cnt[gTokE[t]], 1);
    __syncthreads();
    if (tid == 0) {
        int acc = 0, gc = 0;
        for (int e = 0; e < NEXP; e++) {
            base[e] = acc;
            int ng = (cnt[e] + 255) >> 8;
            for (int i = 0; i < ng && gc < MAXGRP; i++) gGrpE[gc++] = e;
            acc += ng * 256;
        }
        for (; gc < MAXGRP; gc++) gGrpE[gc] = 0;
    }
    __syncthreads();
    for (int r = tid; r < MAXROWS; r += 256) gRowTok[r] = -1;
    __syncthreads();
    for (int t = tid; t < TOKV; t += 256) {
        int e = gTokE[t];
        int s = atomicAdd(&cur[e], 1);
        gRowTok[base[e] + s] = t;
    }
}

// ================= launch 2: gather X + split -> blocked/swizzled ==========
__global__ void gather_k(const float* __restrict__ x) {
    int row = blockIdx.x;
    int tok = gRowTok[row];
    char* bh = (char*)gXh + ((size_t)(row >> 7) * NCH1) * BLKB;
    char* bl = (char*)gXl + ((size_t)(row >> 7) * NCH1) * BLKB;
    int rloc = row & 127;
    for (int k = threadIdx.x * 2; k < DIMV; k += 512) {
        float v0 = 0.f, v1 = 0.f;
        if (tok >= 0) {
            float2 xv = *(const float2*)(x + (size_t)tok * DIMV + k);
            v0 = xv.x; v1 = xv.y;
        }
        bf16 h0, l0, h1, l1;
        split2(v0, h0, l0);
        split2(v1, h1, l1);
        __nv_bfloat162 vh; vh.x = h0; vh.y = h1;
        __nv_bfloat162 vl; vl.x = l0; vl.y = l1;
        size_t blk = (size_t)(k >> 5) * BLKB;
        uint32_t off = SWZ64((uint32_t)(rloc * 64 + (k & 31) * 2));
        *(__nv_bfloat162*)(bh + blk + off) = vh;
        *(__nv_bfloat162*)(bl + blk + off) = vl;
    }
}

// ========= GEMM1: M=128/CTA, bulk-copy fills, depth 2, 2 CTA/SM ============
// smem: [0] tmem ptr, full[2]@16, empty[2]@64, done@112
// stage (48KB): Ah Al B1h B1l B2h B2l (8KB each)
#define G1_STG 49152
#define G1_SMEM (1024 + 2*G1_STG)

__global__ __launch_bounds__(256) void gemm1_tc() {
#if TC_OK
    extern __shared__ char smem[];
    uint32_t sb = smem_u32(smem);
    int tid = threadIdx.x, wid = tid >> 5, lane = tid & 31;
    int tile = blockIdx.y, nbt = blockIdx.x, nb0 = nbt * 128;
    int e = gGrpE[tile >> 1];

    if (wid == 0) tmem_alloc_release(sb, 256);
    if (tid == 0) {
#pragma unroll
        for (int i = 0; i < 2; i++) {
            mbar_init(sb + 16 + i * 8, 1);  // full
            mbar_init(sb + 64 + i * 8, 1);  // empty
        }
        mbar_init(sb + 112, 1);             // done
    }
    __syncthreads();
    uint32_t tmem;
    asm volatile("ld.shared.b32 %0, [%1];" : "=r"(tmem) : "r"(sb));

    const int NS = NCH1;  // 24
    if (wid == 0 && elect1()) {             // producer
        const char* bA_h = (const char*)gXh + ((size_t)tile * NCH1) * BLKB;
        const char* bA_l = (const char*)gXl + ((size_t)tile * NCH1) * BLKB;
        const char* b1h = (const char*)gW1h + ((size_t)(e * 16 + nbt) * NCH1) * BLKB;
        const char* b1l = (const char*)gW1l + ((size_t)(e * 16 + nbt) * NCH1) * BLKB;
        const char* b2h = (const char*)gW2h + ((size_t)(e * 16 + nbt) * NCH1) * BLKB;
        const char* b2l = (const char*)gW2l + ((size_t)(e * 16 + nbt) * NCH1) * BLKB;
        for (int s = 0; s < NS; s++) {
            int b = s & 1;
            if (s >= 2) mbar_wait(sb + 64 + b * 8, (uint32_t)(((s - 2) >> 1) & 1));
            uint32_t st = sb + 1024 + b * G1_STG;
            uint32_t fb = sb + 16 + b * 8;
            size_t o = (size_t)s * BLKB;
            expect_tx(fb, 49152);
            blkcp(st,         bA_h + o, BLKB, fb);
            blkcp(st + 8192,  bA_l + o, BLKB, fb);
            blkcp(st + 16384, b1h + o, BLKB, fb);
            blkcp(st + 24576, b1l + o, BLKB, fb);
            blkcp(st + 32768, b2h + o, BLKB, fb);
            blkcp(st + 40960, b2l + o, BLKB, fb);
        }
    }
    if (wid == 1) {                          // consumer (MMA)
        for (int s = 0; s < NS; s++) {
            int b = s & 1;
            mbar_wait(sb + 16 + b * 8, (uint32_t)((s >> 1) & 1));
            if (elect1()) {
                uint32_t st = sb + 1024 + b * G1_STG;
                uint64_t ah = desc64(st), al = desc64(st + 8192);
                uint64_t b1h = desc64(st + 16384), b1l = desc64(st + 24576);
                uint64_t b2h = desc64(st + 32768), b2l = desc64(st + 40960);
                uint32_t D1 = tmem, D2 = tmem + 128;
#pragma unroll
                for (int k = 0; k < 2; k++) {
                    uint32_t en = (s == 0 && k == 0) ? 0u : 1u;
                    uint64_t k2 = (uint64_t)(k * 2);
                    mma_ss(D1, ah + k2, b1h + k2, en);
                    mma_ss(D1, ah + k2, b1l + k2, 1u);
                    mma_ss(D1, al + k2, b1h + k2, 1u);
                    mma_ss(D2, ah + k2, b2h + k2, en);
                    mma_ss(D2, ah + k2, b2l + k2, 1u);
                    mma_ss(D2, al + k2, b2h + k2, 1u);
                }
                mma_commit(sb + 64 + b * 8);
            }
        }
        if (elect1()) mma_commit(sb + 112);
    }

    mbar_wait(sb + 112, 0);
    tm_fence_after();

    {
        int sub = wid & 3, chalf = wid >> 2;
        int rloc = sub * 32 + lane;
        char* uh = (char*)gUh + ((size_t)tile * NCH2) * BLKB;
        char* ul = (char*)gUl + ((size_t)tile * NCH2) * BLKB;
#pragma unroll
        for (int p = 0; p < 2; p++) {
            uint32_t r1[32], r2[32];
            ldtm32(r1, tmem + chalf * 64 + p * 32);
            ldtm32(r2, tmem + 128 + chalf * 64 + p * 32);
            tm_wait_ld();
            int kchunk = (nb0 >> 5) + chalf * 2 + p;
            size_t blk = (size_t)kchunk * BLKB;
#pragma unroll
            for (int j = 0; j < 32; j += 2) {
                float h1a = __uint_as_float(r1[j]),     h2a = __uint_as_float(r2[j]);
                float h1b = __uint_as_float(r1[j + 1]), h2b = __uint_as_float(r2[j + 1]);
                float ua = h1a * (1.f / (1.f + expf(-h1a))) * h2a;
                float ub = h1b * (1.f / (1.f + expf(-h1b))) * h2b;
                bf16 ha, la, hb, lb;
                split2(ua, ha, la);
                split2(ub, hb, lb);
                __nv_bfloat162 vh; vh.x = ha; vh.y = hb;
                __nv_bfloat162 vl; vl.x = la; vl.y = lb;
                uint32_t off = SWZ64((uint32_t)(rloc * 64 + j * 2));
                *(__nv_bfloat162*)(uh + blk + off) = vh;
                *(__nv_bfloat162*)(ul + blk + off) = vl;
            }
        }
    }
    __syncthreads();
    if (tid == 0) {
#pragma unroll
        for (int i = 0; i < 2; i++) { mbar_inval(sb + 16 + i * 8); mbar_inval(sb + 64 + i * 8); }
        mbar_inval(sb + 112);
    }
    __syncthreads();
    if (wid == 0) tmem_dealloc(tmem, 256);
#endif
}

// ========= GEMM2: M=128/CTA, bulk-copy fills, depth 3, 2 CTA/SM ============
// stage (32KB): Ah Al Bh Bl (8KB each)
#define G2_STG 32768
#define G2_SMEM (1024 + 3*G2_STG)

__global__ __launch_bounds__(256) void gemm2_tc(float* __restrict__ out) {
#if TC_OK
    extern __shared__ char smem[];
    uint32_t sb = smem_u32(smem);
    int tid = threadIdx.x, wid = tid >> 5, lane = tid & 31;
    int tile = blockIdx.y, nbt = blockIdx.x, nb0 = nbt * 128;
    int e = gGrpE[tile >> 1];

    if (wid == 0) tmem_alloc_release(sb, 128);
    if (tid == 0) {
#pragma unroll
        for (int i = 0; i < 3; i++) {
            mbar_init(sb + 16 + i * 8, 1);
            mbar_init(sb + 64 + i * 8, 1);
        }
        mbar_init(sb + 112, 1);
    }
    __syncthreads();
    uint32_t tmem;
    asm volatile("ld.shared.b32 %0, [%1];" : "=r"(tmem) : "r"(sb));

    const int NS = NCH2;  // 64
    if (wid == 0 && elect1()) {
        const char* bA_h = (const char*)gUh + ((size_t)tile * NCH2) * BLKB;
        const char* bA_l = (const char*)gUl + ((size_t)tile * NCH2) * BLKB;
        const char* bBh = (const char*)gW3h + ((size_t)(e * 6 + nbt) * NCH2) * BLKB;
        const char* bBl = (const char*)gW3l + ((size_t)(e * 6 + nbt) * NCH2) * BLKB;
        for (int s = 0; s < NS; s++) {
            int b = s % 3;
            if (s >= 3) mbar_wait(sb + 64 + b * 8, (uint32_t)(((s - 3) / 3) & 1));
            uint32_t st = sb + 1024 + b * G2_STG;
            uint32_t fb = sb + 16 + b * 8;
            size_t o = (size_t)s * BLKB;
            expect_tx(fb, 32768);
            blkcp(st,         bA_h + o, BLKB, fb);
            blkcp(st + 8192,  bA_l + o, BLKB, fb);
            blkcp(st + 16384, bBh + o, BLKB, fb);
            blkcp(st + 24576, bBl + o, BLKB, fb);
        }
    }
    if (wid == 1) {
        for (int s = 0; s < NS; s++) {
            int b = s % 3;
            mbar_wait(sb + 16 + b * 8, (uint32_t)((s / 3) & 1));
            if (elect1()) {
                uint32_t st = sb + 1024 + b * G2_STG;
                uint64_t ah = desc64(st), al = desc64(st + 8192);
                uint64_t bh = desc64(st + 16384), bl = desc64(st + 24576);
#pragma unroll
                for (int k = 0; k < 2; k++) {
                    uint32_t en = (s == 0 && k == 0) ? 0u : 1u;
                    uint64_t k2 = (uint64_t)(k * 2);
                    mma_ss(tmem, ah + k2, bh + k2, en);
                    mma_ss(tmem, ah + k2, bl + k2, 1u);
                    mma_ss(tmem, al + k2, bh + k2, 1u);
                }
                mma_commit(sb + 64 + b * 8);
            }
        }
        if (elect1()) mma_commit(sb + 112);
    }

    mbar_wait(sb + 112, 0);
    tm_fence_after();

    {
        int sub = wid & 3, chalf = wid >> 2;
        int grow = tile * 128 + sub * 32 + lane;
        int tok = gRowTok[grow];
        float p = (tok >= 0) ? gP[tok] : 0.f;
        float* o = (tok >= 0) ? (out + (size_t)tok * DIMV + nb0 + chalf * 64) : nullptr;
#pragma unroll
        for (int pq = 0; pq < 2; pq++) {
            uint32_t r[32];
            ldtm32(r, tmem + chalf * 64 + pq * 32);
            tm_wait_ld();
            if (tok >= 0) {
#pragma unroll
                for (int j = 0; j < 32; j++)
                    o[pq * 32 + j] =
                        __bfloat162float(__float2bfloat16(__uint_as_float(r[j]))) * p;
            }
        }
    }
    __syncthreads();
    if (tid == 0) {
#pragma unroll
        for (int i = 0; i < 3; i++) { mbar_inval(sb + 16 + i * 8); mbar_inval(sb + 64 + i * 8); }
        mbar_inval(sb + 112);
    }
    __syncthreads();
    if (wid == 0) tmem_dealloc(tmem, 128);
#endif
}

// ------------------------- launcher ----------------------------------------
extern "C" void kernel_launch(void* const* d_in, const int* in_sizes, int n_in,
                              void* d_out, int out_size) {
    const float* x  = (const float*)d_in[0];
    const float* rw = (const float*)d_in[1];
    const float* rb = (const float*)d_in[2];
    const float* w1 = (const float*)d_in[3];
    const float* w2 = (const float*)d_in[4];
    const float* w3 = (const float*)d_in[5];
    float* out = (float*)d_out;

    cudaFuncSetAttribute(gemm1_tc, cudaFuncAttributeMaxDynamicSharedMemorySize, G1_SMEM);
    cudaFuncSetAttribute(gemm2_tc, cudaFuncAttributeMaxDynamicSharedMemorySize, G2_SMEM);

    tsplit_all_k<<<dim3(32, 32, 24), 256>>>(w1, w2, w3);        // 0
    routerplan_k<<<512, 256>>>(x, rw, rb);                      // 1
    gather_k<<<MAXROWS, 256>>>(x);                              // 2
    gemm1_tc<<<dim3(HIDV / 128, NTILE), 256, G1_SMEM>>>();      // 3 (profiled)
    gemm2_tc<<<dim3(DIMV / 128, NTILE), 256, G2_SMEM>>>(out);   // 4
}

// round 14
// speedup vs baseline: 1.2644x; 1.0723x over previous
#include <cuda_runtime.h>
#include <cuda_bf16.h>
#include <cstdint>

typedef __nv_bfloat16 bf16;

#if defined(__CUDA_ARCH__) && (__CUDA_ARCH__ == 1030) && \
    (defined(__CUDA_ARCH_FEAT_SM103_ALL) || defined(__CUDA_ARCH_FEAT_SM100_ALL))
#define TC_OK 1
#else
#define TC_OK 0
#endif

#define DIMV 768
#define HIDV 2048
#define TOKV 4096
#define NEXP 8
#define MAXGRP 24
#define NTILE (MAXGRP*2)      // 48 row-tiles of 128
#define MAXROWS (MAXGRP*256)
#define KC 32                 // stage K elems -> 8KB blocks (128 x 64B, SW64)
#define NCH1 (DIMV/KC)        // 24 k-chunks (X, W1, W2)
#define NCH2 (HIDV/KC)        // 64 k-chunks (U, W3)
#define BLKB 8192             // bytes per block

// ------------------------- device scratch (blocked, pre-swizzled) ----------
// W1/W2: [e][n_tile 16][k_chunk 24][8KB]   W3: [e][n_tile 6][k_chunk 64][8KB]
// X: [tile 48][k_chunk 24][8KB]            U: [tile 48][k_chunk 64][8KB]
__device__ bf16 gW1h[(size_t)NEXP*HIDV*DIMV];
__device__ bf16 gW1l[(size_t)NEXP*HIDV*DIMV];
__device__ bf16 gW2h[(size_t)NEXP*HIDV*DIMV];
__device__ bf16 gW2l[(size_t)NEXP*HIDV*DIMV];
__device__ bf16 gW3h[(size_t)NEXP*DIMV*HIDV];
__device__ bf16 gW3l[(size_t)NEXP*DIMV*HIDV];
__device__ bf16 gXh[(size_t)MAXROWS*DIMV];
__device__ bf16 gXl[(size_t)MAXROWS*DIMV];
__device__ bf16 gUh[(size_t)MAXROWS*HIDV];
__device__ bf16 gUl[(size_t)MAXROWS*HIDV];
__device__ int   gTokE[TOKV];
__device__ float gP[TOKV];
__device__ int   gRowTok[MAXROWS];
__device__ int   gGrpE[MAXGRP];
__device__ int   gDone;

// ------------------------- common helpers ----------------------------------
__device__ __forceinline__ uint32_t smem_u32(const void* p) {
    uint32_t a;
    asm("{ .reg .u64 t; cvta.to.shared.u64 t, %1; cvt.u32.u64 %0, t; }" : "=r"(a) : "l"(p));
    return a;
}
__device__ __forceinline__ void split2(float v, bf16& h, bf16& l) {
    h = __float2bfloat16(v);
    l = __float2bfloat16(v - __bfloat162float(h));
}
#define SWZ64(x) ((x) ^ (((x) >> 3) & 0x30))

// ------------------------- tcgen05 / bulk-copy helpers ---------------------
__device__ __forceinline__ uint32_t elect1() {
    uint32_t p = 0;
#if TC_OK
    asm volatile("{ .reg .pred p; elect.sync _|p, 0xFFFFFFFF; selp.b32 %0,1,0,p; }" : "=r"(p));
#endif
    return p;
}
__device__ __forceinline__ uint64_t desc64(uint32_t addr) {
    // SW64: layout=4, version=1, SBO=32 (512B), LBO=1 (16B) — validated R5
    const uint64_t base = (uint64_t(4) << 61) | (uint64_t(1) << 46)
                        | (uint64_t(32) << 32) | (uint64_t(1) << 16);
    return base | ((uint64_t)(addr >> 4) & 0x3FFF);
}
#define IDESC 0x8200490u   // kind::f16, bf16 x bf16 -> f32, M=128, N=128

__device__ __forceinline__ void mma_ss(uint32_t d, uint64_t ad, uint64_t bd, uint32_t en) {
#if TC_OK
    asm volatile(
        "{\n .reg .pred p;\n setp.ne.u32 p, %4, 0;\n"
        " tcgen05.mma.cta_group::1.kind::f16 [%0], %1, %2, %3, {%5,%5,%5,%5}, p;\n}"
        :: "r"(d), "l"(ad), "l"(bd), "r"(IDESC), "r"(en), "r"(0u) : "memory");
#endif
}
__device__ __forceinline__ void mma_commit(uint32_t mbar) {
#if TC_OK
    asm volatile(
        "tcgen05.commit.cta_group::1.mbarrier::arrive::one.shared::cluster.b64 [%0];"
        :: "r"(mbar) : "memory");
#endif
}
// contiguous 1D bulk copy GMEM->SMEM (UBLKCP), complete_tx on mbar
__device__ __forceinline__ void blkcp(uint32_t dst, const void* src, uint32_t bytes,
                                      uint32_t mbar) {
#if TC_OK
    asm volatile(
        "cp.async.bulk.shared::cluster.global.mbarrier::complete_tx::bytes "
        "[%0], [%1], %2, [%3];"
        :: "r"(dst), "l"(src), "r"(bytes), "r"(mbar) : "memory");
#endif
}
__device__ __forceinline__ void expect_tx(uint32_t mbar, uint32_t bytes) {
#if TC_OK
    asm volatile("mbarrier.arrive.expect_tx.shared.b64 _, [%0], %1;"
                 :: "r"(mbar), "r"(bytes) : "memory");
#endif
}
__device__ __forceinline__ void mbar_init(uint32_t a, uint32_t c) {
#if TC_OK
    asm volatile("mbarrier.init.shared.b64 [%0], %1;" :: "r"(a), "r"(c) : "memory");
#endif
}
__device__ __forceinline__ void mbar_inval(uint32_t a) {
#if TC_OK
    asm volatile("mbarrier.inval.shared.b64 [%0];" :: "r"(a) : "memory");
#endif
}
__device__ __forceinline__ void mbar_wait(uint32_t a, uint32_t ph) {
#if TC_OK
    uint32_t ok = 0;
    while (!ok) {
        asm volatile(
            "{\n .reg .pred P;\n"
            " mbarrier.try_wait.parity.acquire.cta.shared::cta.b64 P, [%1], %2, 0x989680;\n"
            " selp.b32 %0, 1, 0, P;\n}"
            : "=r"(ok) : "r"(a), "r"(ph) : "memory");
    }
#endif
}
// alloc + IMMEDIATE permit relinquish (R12 fix: keeps 2nd CTA from blocking)
__device__ __forceinline__ void tmem_alloc_release(uint32_t smem_ptr, uint32_t ncols) {
#if TC_OK
    asm volatile("tcgen05.alloc.cta_group::1.sync.aligned.shared::cta.b32 [%0], %1;"
                 :: "r"(smem_ptr), "r"(ncols) : "memory");
    asm volatile("tcgen05.relinquish_alloc_permit.cta_group::1.sync.aligned;");
#endif
}
__device__ __forceinline__ void tmem_dealloc(uint32_t tmem, uint32_t ncols) {
#if TC_OK
    asm volatile("tcgen05.dealloc.cta_group::1.sync.aligned.b32 %0, %1;" :: "r"(tmem), "r"(ncols));
#endif
}
__device__ __forceinline__ void ldtm32(uint32_t* r, uint32_t ta) {
#if TC_OK
    asm volatile(
        "tcgen05.ld.sync.aligned.32x32b.x32.b32 "
        "{%0,%1,%2,%3,%4,%5,%6,%7,%8,%9,%10,%11,%12,%13,%14,%15,"
        "%16,%17,%18,%19,%20,%21,%22,%23,%24,%25,%26,%27,%28,%29,%30,%31}, [%32];"
        : "=r"(r[0]), "=r"(r[1]), "=r"(r[2]), "=r"(r[3]), "=r"(r[4]), "=r"(r[5]),
          "=r"(r[6]), "=r"(r[7]), "=r"(r[8]), "=r"(r[9]), "=r"(r[10]), "=r"(r[11]),
          "=r"(r[12]), "=r"(r[13]), "=r"(r[14]), "=r"(r[15]), "=r"(r[16]), "=r"(r[17]),
          "=r"(r[18]), "=r"(r[19]), "=r"(r[20]), "=r"(r[21]), "=r"(r[22]), "=r"(r[23]),
          "=r"(r[24]), "=r"(r[25]), "=r"(r[26]), "=r"(r[27]), "=r"(r[28]), "=r"(r[29]),
          "=r"(r[30]), "=r"(r[31])
        : "r"(ta));
#endif
}
__device__ __forceinline__ void tm_wait_ld() {
#if TC_OK
    asm volatile("tcgen05.wait::ld.sync.aligned;" ::: "memory");
#endif
}
__device__ __forceinline__ void tm_fence_after() {
#if TC_OK
    asm volatile("tcgen05.fence::after_thread_sync;" ::: "memory");
#endif
}

// ================= launch 0: weight transpose + split -> blocked/swizzled ==
__global__ void tsplit_all_k(const float* __restrict__ w1,
                             const float* __restrict__ w2,
                             const float* __restrict__ w3) {
    __shared__ float tile[64][65];
    int z = blockIdx.z;
    if (z == 0 && blockIdx.x == 0 && blockIdx.y == 0 && threadIdx.x == 0) gDone = 0;
    int R, C, e;
    const float* src;
    char *dh, *dl;
    int ntile, nch;
    if (z < 16) {
        R = DIMV; C = HIDV; e = z & 7;
        src = (z < 8) ? w1 : w2;
        dh = (char*)((z < 8) ? gW1h : gW2h);
        dl = (char*)((z < 8) ? gW1l : gW2l);
        ntile = 16; nch = NCH1;
        if ((int)blockIdx.y >= R / 64) return;
    } else {
        R = HIDV; C = DIMV; e = z - 16;
        src = w3; dh = (char*)gW3h; dl = (char*)gW3l;
        ntile = 6; nch = NCH2;
        if ((int)blockIdx.x >= C / 64) return;
    }
    int c0 = blockIdx.x * 64, r0 = blockIdx.y * 64;
    int tid = threadIdx.x;
    const float* s = src + (size_t)e * R * C;
#pragma unroll
    for (int i = 0; i < 16; i++) {
        int idx = i * 256 + tid;
        int r = idx >> 6, c = idx & 63;
        tile[r][c] = s[(size_t)(r0 + r) * C + c0 + c];
    }
    __syncthreads();
#pragma unroll
    for (int i = 0; i < 8; i++) {
        int idx = i * 256 + tid;
        int c = idx >> 5, rp = idx & 31, r = rp * 2;
        float v0 = tile[r][c], v1 = tile[r + 1][c];
        bf16 h0, l0, h1, l1;
        split2(v0, h0, l0);
        split2(v1, h1, l1);
        __nv_bfloat162 vh; vh.x = h0; vh.y = h1;
        __nv_bfloat162 vl; vl.x = l0; vl.y = l1;
        int n = c0 + c;          // N-dim index
        int k = r0 + r;          // K-dim index
        size_t blk = ((size_t)(e * ntile + (n >> 7)) * nch + (k >> 5)) * BLKB;
        uint32_t off = SWZ64((uint32_t)((n & 127) * 64 + (k & 31) * 2));
        *(__nv_bfloat162*)(dh + blk + off) = vh;
        *(__nv_bfloat162*)(dl + blk + off) = vl;
    }
}

// ========== launch 1: router + (last block) plan ===========================
__global__ void routerplan_k(const float* __restrict__ x,
                             const float* __restrict__ rw,
                             const float* __restrict__ rb) {
    int tid = threadIdx.x;
    int warp = tid >> 5, lane = tid & 31;
    int tok = blockIdx.x * 8 + warp;
    {
        const float* xr = x + (size_t)tok * DIMV;
        float acc[NEXP];
#pragma unroll
        for (int e = 0; e < NEXP; e++) acc[e] = 0.f;
        for (int k = lane; k < DIMV; k += 32) {
            float xv = xr[k];
            const float* w = rw + k * NEXP;
#pragma unroll
            for (int e = 0; e < NEXP; e++) acc[e] += xv * w[e];
        }
#pragma unroll
        for (int off = 16; off; off >>= 1)
#pragma unroll
            for (int e = 0; e < NEXP; e++)
                acc[e] += __shfl_xor_sync(0xffffffffu, acc[e], off);
        if (lane == 0) {
            float l[NEXP];
            float m = -1e30f; int mi = 0;
#pragma unroll
            for (int e = 0; e < NEXP; e++) {
                l[e] = acc[e] + rb[e];
                if (l[e] > m) { m = l[e]; mi = e; }
            }
            float s = 0.f;
#pragma unroll
            for (int e = 0; e < NEXP; e++) s += expf(l[e] - m);
            gTokE[tok] = mi;
            gP[tok] = 1.f / s;
        }
    }
    __shared__ int sLast;
    __threadfence();
    __syncthreads();
    if (tid == 0) {
        int v = atomicAdd(&gDone, 1);
        sLast = (v == (int)gridDim.x - 1) ? 1 : 0;
    }
    __syncthreads();
    if (!sLast) return;

    __shared__ int cnt[NEXP], cur[NEXP], base[NEXP];
    if (tid < NEXP) { cnt[tid] = 0; cur[tid] = 0; }
    __syncthreads();
    for (int t = tid; t < TOKV; t += 256) atomicAdd(&cnt[gTokE[t]], 1);
    __syncthreads();
    if (tid == 0) {
        int acc = 0, gc = 0;
        for (int e = 0; e < NEXP; e++) {
            base[e] = acc;
            int ng = (cnt[e] + 255) >> 8;
            for (int i = 0; i < ng && gc < MAXGRP; i++) gGrpE[gc++] = e;
            acc += ng * 256;
        }
        for (; gc < MAXGRP; gc++) gGrpE[gc] = 0;
    }
    __syncthreads();
    for (int r = tid; r < MAXROWS; r += 256) gRowTok[r] = -1;
    __syncthreads();
    for (int t = tid; t < TOKV; t += 256) {
        int e = gTokE[t];
        int s = atomicAdd(&cur[e], 1);
        gRowTok[base[e] + s] = t;
    }
}

// ================= launch 2: gather X + split -> blocked/swizzled ==========
__global__ void gather_k(const float* __restrict__ x) {
    int row = blockIdx.x;
    int tok = gRowTok[row];
    char* bh = (char*)gXh + ((size_t)(row >> 7) * NCH1) * BLKB;
    char* bl = (char*)gXl + ((size_t)(row >> 7) * NCH1) * BLKB;
    int rloc = row & 127;
    for (int k = threadIdx.x * 2; k < DIMV; k += 512) {
        float v0 = 0.f, v1 = 0.f;
        if (tok >= 0) {
            float2 xv = *(const float2*)(x + (size_t)tok * DIMV + k);
            v0 = xv.x; v1 = xv.y;
        }
        bf16 h0, l0, h1, l1;
        split2(v0, h0, l0);
        split2(v1, h1, l1);
        __nv_bfloat162 vh; vh.x = h0; vh.y = h1;
        __nv_bfloat162 vl; vl.x = l0; vl.y = l1;
        size_t blk = (size_t)(k >> 5) * BLKB;
        uint32_t off = SWZ64((uint32_t)(rloc * 64 + (k & 31) * 2));
        *(__nv_bfloat162*)(bh + blk + off) = vh;
        *(__nv_bfloat162*)(bl + blk + off) = vl;
    }
}

// ========= GEMM1: M=128/CTA, bulk-copy fills, depth 2, 2 CTA/SM ============
// smem: [0] tmem ptr, full[2]@16, empty[2]@64, done@112
// stage (48KB): Ah Al B1h B1l B2h B2l (8KB each)
#define G1_STG 49152
#define G1_SMEM (1024 + 2*G1_STG)

__global__ __launch_bounds__(256, 2) void gemm1_tc() {
#if TC_OK
    extern __shared__ char smem[];
    uint32_t sb = smem_u32(smem);
    int tid = threadIdx.x, wid = tid >> 5, lane = tid & 31;
    int tile = blockIdx.y, nbt = blockIdx.x, nb0 = nbt * 128;
    int e = gGrpE[tile >> 1];

    if (wid == 0) tmem_alloc_release(sb, 256);
    if (tid == 0) {
#pragma unroll
        for (int i = 0; i < 2; i++) {
            mbar_init(sb + 16 + i * 8, 1);  // full
            mbar_init(sb + 64 + i * 8, 1);  // empty
        }
        mbar_init(sb + 112, 1);             // done
    }
    __syncthreads();
    uint32_t tmem;
    asm volatile("ld.shared.b32 %0, [%1];" : "=r"(tmem) : "r"(sb));

    const int NS = NCH1;  // 24
    if (wid == 0 && elect1()) {             // producer
        const char* bA_h = (const char*)gXh + ((size_t)tile * NCH1) * BLKB;
        const char* bA_l = (const char*)gXl + ((size_t)tile * NCH1) * BLKB;
        const char* b1h = (const char*)gW1h + ((size_t)(e * 16 + nbt) * NCH1) * BLKB;
        const char* b1l = (const char*)gW1l + ((size_t)(e * 16 + nbt) * NCH1) * BLKB;
        const char* b2h = (const char*)gW2h + ((size_t)(e * 16 + nbt) * NCH1) * BLKB;
        const char* b2l = (const char*)gW2l + ((size_t)(e * 16 + nbt) * NCH1) * BLKB;
        for (int s = 0; s < NS; s++) {
            int b = s & 1;
            if (s >= 2) mbar_wait(sb + 64 + b * 8, (uint32_t)(((s - 2) >> 1) & 1));
            uint32_t st = sb + 1024 + b * G1_STG;
            uint32_t fb = sb + 16 + b * 8;
            size_t o = (size_t)s * BLKB;
            expect_tx(fb, 49152);
            blkcp(st,         bA_h + o, BLKB, fb);
            blkcp(st + 8192,  bA_l + o, BLKB, fb);
            blkcp(st + 16384, b1h + o, BLKB, fb);
            blkcp(st + 24576, b1l + o, BLKB, fb);
            blkcp(st + 32768, b2h + o, BLKB, fb);
            blkcp(st + 40960, b2l + o, BLKB, fb);
        }
    }
    if (wid == 1) {                          // consumer (MMA)
        for (int s = 0; s < NS; s++) {
            int b = s & 1;
            mbar_wait(sb + 16 + b * 8, (uint32_t)((s >> 1) & 1));
            if (elect1()) {
                uint32_t st = sb + 1024 + b * G1_STG;
                uint64_t ah = desc64(st), al = desc64(st + 8192);
                uint64_t b1h = desc64(st + 16384), b1l = desc64(st + 24576);
                uint64_t b2h = desc64(st + 32768), b2l = desc64(st + 40960);
                uint32_t D1 = tmem, D2 = tmem + 128;
#pragma unroll
                for (int k = 0; k < 2; k++) {
                    uint32_t en = (s == 0 && k == 0) ? 0u : 1u;
                    uint64_t k2 = (uint64_t)(k * 2);
                    mma_ss(D1, ah + k2, b1h + k2, en);
                    mma_ss(D1, ah + k2, b1l + k2, 1u);
                    mma_ss(D1, al + k2, b1h + k2, 1u);
                    mma_ss(D2, ah + k2, b2h + k2, en);
                    mma_ss(D2, ah + k2, b2l + k2, 1u);
                    mma_ss(D2, al + k2, b2h + k2, 1u);
                }
                mma_commit(sb + 64 + b * 8);
            }
        }
        if (elect1()) mma_commit(sb + 112);
    }

    mbar_wait(sb + 112, 0);
    tm_fence_after();

    {
        int sub = wid & 3, chalf = wid >> 2;
        int rloc = sub * 32 + lane;
        char* uh = (char*)gUh + ((size_t)tile * NCH2) * BLKB;
        char* ul = (char*)gUl + ((size_t)tile * NCH2) * BLKB;
#pragma unroll
        for (int p = 0; p < 2; p++) {
            uint32_t r1[32], r2[32];
            ldtm32(r1, tmem + chalf * 64 + p * 32);
            ldtm32(r2, tmem + 128 + chalf * 64 + p * 32);
            tm_wait_ld();
            int kchunk = (nb0 >> 5) + chalf * 2 + p;
            size_t blk = (size_t)kchunk * BLKB;
#pragma unroll
            for (int j = 0; j < 32; j += 2) {
                float h1a = __uint_as_float(r1[j]),     h2a = __uint_as_float(r2[j]);
                float h1b = __uint_as_float(r1[j + 1]), h2b = __uint_as_float(r2[j + 1]);
                float ua = h1a * (1.f / (1.f + expf(-h1a))) * h2a;
                float ub = h1b * (1.f / (1.f + expf(-h1b))) * h2b;
                bf16 ha, la, hb, lb;
                split2(ua, ha, la);
                split2(ub, hb, lb);
                __nv_bfloat162 vh; vh.x = ha; vh.y = hb;
                __nv_bfloat162 vl; vl.x = la; vl.y = lb;
                uint32_t off = SWZ64((uint32_t)(rloc * 64 + j * 2));
                *(__nv_bfloat162*)(uh + blk + off) = vh;
                *(__nv_bfloat162*)(ul + blk + off) = vl;
            }
        }
    }
    __syncthreads();
    if (tid == 0) {
#pragma unroll
        for (int i = 0; i < 2; i++) { mbar_inval(sb + 16 + i * 8); mbar_inval(sb + 64 + i * 8); }
        mbar_inval(sb + 112);
    }
    __syncthreads();
    if (wid == 0) tmem_dealloc(tmem, 256);
#endif
}

// ========= GEMM2: M=128/CTA, bulk-copy fills, depth 3, 2 CTA/SM ============
// stage (32KB): Ah Al Bh Bl (8KB each)
#define G2_STG 32768
#define G2_SMEM (1024 + 3*G2_STG)

__global__ __launch_bounds__(256, 2) void gemm2_tc(float* __restrict__ out) {
#if TC_OK
    extern __shared__ char smem[];
    uint32_t sb = smem_u32(smem);
    int tid = threadIdx.x, wid = tid >> 5, lane = tid & 31;
    int tile = blockIdx.y, nbt = blockIdx.x, nb0 = nbt * 128;
    int e = gGrpE[tile >> 1];

    if (wid == 0) tmem_alloc_release(sb, 128);
    if (tid == 0) {
#pragma unroll
        for (int i = 0; i < 3; i++) {
            mbar_init(sb + 16 + i * 8, 1);
            mbar_init(sb + 64 + i * 8, 1);
        }
        mbar_init(sb + 112, 1);
    }
    __syncthreads();
    uint32_t tmem;
    asm volatile("ld.shared.b32 %0, [%1];" : "=r"(tmem) : "r"(sb));

    const int NS = NCH2;  // 64
    if (wid == 0 && elect1()) {
        const char* bA_h = (const char*)gUh + ((size_t)tile * NCH2) * BLKB;
        const char* bA_l = (const char*)gUl + ((size_t)tile * NCH2) * BLKB;
        const char* bBh = (const char*)gW3h + ((size_t)(e * 6 + nbt) * NCH2) * BLKB;
        const char* bBl = (const char*)gW3l + ((size_t)(e * 6 + nbt) * NCH2) * BLKB;
        for (int s = 0; s < NS; s++) {
            int b = s % 3;
            if (s >= 3) mbar_wait(sb + 64 + b * 8, (uint32_t)(((s - 3) / 3) & 1));
            uint32_t st = sb + 1024 + b * G2_STG;
            uint32_t fb = sb + 16 + b * 8;
            size_t o = (size_t)s * BLKB;
            expect_tx(fb, 32768);
            blkcp(st,         bA_h + o, BLKB, fb);
            blkcp(st + 8192,  bA_l + o, BLKB, fb);
            blkcp(st + 16384, bBh + o, BLKB, fb);
            blkcp(st + 24576, bBl + o, BLKB, fb);
        }
    }
    if (wid == 1) {
        for (int s = 0; s < NS; s++) {
            int b = s % 3;
            mbar_wait(sb + 16 + b * 8, (uint32_t)((s / 3) & 1));
            if (elect1()) {
                uint32_t st = sb + 1024 + b * G2_STG;
                uint64_t ah = desc64(st), al = desc64(st + 8192);
                uint64_t bh = desc64(st + 16384), bl = desc64(st + 24576);
#pragma unroll
                for (int k = 0; k < 2; k++) {
                    uint32_t en = (s == 0 && k == 0) ? 0u : 1u;
                    uint64_t k2 = (uint64_t)(k * 2);
                    mma_ss(tmem, ah + k2, bh + k2, en);
                    mma_ss(tmem, ah + k2, bl + k2, 1u);
                    mma_ss(tmem, al + k2, bh + k2, 1u);
                }
                mma_commit(sb + 64 + b * 8);
            }
        }
        if (elect1()) mma_commit(sb + 112);
    }

    mbar_wait(sb + 112, 0);
    tm_fence_after();

    {
        int sub = wid & 3, chalf = wid >> 2;
        int grow = tile * 128 + sub * 32 + lane;
        int tok = gRowTok[grow];
        float p = (tok >= 0) ? gP[tok] : 0.f;
        float* o = (tok >= 0) ? (out + (size_t)tok * DIMV + nb0 + chalf * 64) : nullptr;
#pragma unroll
        for (int pq = 0; pq < 2; pq++) {
            uint32_t r[32];
            ldtm32(r, tmem + chalf * 64 + pq * 32);
            tm_wait_ld();
            if (tok >= 0) {
#pragma unroll
                for (int j = 0; j < 32; j++)
                    o[pq * 32 + j] =
                        __bfloat162float(__float2bfloat16(__uint_as_float(r[j]))) * p;
            }
        }
    }
    __syncthreads();
    if (tid == 0) {
#pragma unroll
        for (int i = 0; i < 3; i++) { mbar_inval(sb + 16 + i * 8); mbar_inval(sb + 64 + i * 8); }
        mbar_inval(sb + 112);
    }
    __syncthreads();
    if (wid == 0) tmem_dealloc(tmem, 128);
#endif
}

// ------------------------- launcher ----------------------------------------
extern "C" void kernel_launch(void* const* d_in, const int* in_sizes, int n_in,
                              void* d_out, int out_size) {
    const float* x  = (const float*)d_in[0];
    const float* rw = (const float*)d_in[1];
    const float* rb = (const float*)d_in[2];
    const float* w1 = (const float*)d_in[3];
    const float* w2 = (const float*)d_in[4];
    const float* w3 = (const float*)d_in[5];
    float* out = (float*)d_out;

    cudaFuncSetAttribute(gemm1_tc, cudaFuncAttributeMaxDynamicSharedMemorySize, G1_SMEM);
    cudaFuncSetAttribute(gemm2_tc, cudaFuncAttributeMaxDynamicSharedMemorySize, G2_SMEM);

    tsplit_all_k<<<dim3(32, 32, 24), 256>>>(w1, w2, w3);        // 0
    routerplan_k<<<512, 256>>>(x, rw, rb);                      // 1
    gather_k<<<MAXROWS, 256>>>(x);                              // 2
    gemm1_tc<<<dim3(HIDV / 128, NTILE), 256, G1_SMEM>>>();      // 3 (profiled)
    gemm2_tc<<<dim3(DIMV / 128, NTILE), 256, G2_SMEM>>>(out);   // 4
}